// round 8
// baseline (speedup 1.0000x reference)
#include <cuda_runtime.h>
#include <cuda_bf16.h>
#include <cstdint>
#include <math.h>

typedef __nv_bfloat16 bf16;

#define NTOK 8192
#define DDIM 2048
#define KDIM 2048
#define SCALING_F (16.0f / 2048.0f)
#define EPS_F 1e-12f

// Per-tensor fp8 scales (powers of 2). lo parts additionally pre-scaled by 2^9.
#define SX  4.0f
#define SW  512.0f
#define SP  1024.0f
#define SQT 2048.0f
#define S_LO 512.0f   // 2^9

// ---------------------------------------------------------------------------
// Static device scratch
// ---------------------------------------------------------------------------
__device__ __align__(256) bf16    g_x_hi [(size_t)NTOK * DDIM];
__device__ __align__(256) uint8_t g_x8h  [(size_t)NTOK * DDIM];
__device__ __align__(256) uint8_t g_x8l  [(size_t)NTOK * DDIM];
__device__ __align__(256) bf16    g_lB_hi[(size_t)DDIM * DDIM];
__device__ __align__(256) uint8_t g_lB8h [(size_t)DDIM * DDIM];
__device__ __align__(256) uint8_t g_lB8l [(size_t)DDIM * DDIM];
__device__ __align__(256) bf16    g_lAT_hi[(size_t)DDIM * DDIM];
__device__ __align__(256) uint8_t g_lAT8h[(size_t)DDIM * DDIM];
__device__ __align__(256) uint8_t g_lAT8l[(size_t)DDIM * DDIM];
__device__ __align__(256) bf16    g_dir_hi[(size_t)DDIM * DDIM];
__device__ __align__(256) uint8_t g_dir8h[(size_t)DDIM * DDIM];
__device__ __align__(256) uint8_t g_dir8l[(size_t)DDIM * DDIM];
__device__ __align__(256) bf16    g_P_hi [(size_t)DDIM * DDIM];
__device__ __align__(256) uint8_t g_P8h  [(size_t)DDIM * DDIM];
__device__ __align__(256) uint8_t g_P8l  [(size_t)DDIM * DDIM];
__device__ __align__(256) bf16    g_QT_hi[(size_t)DDIM * DDIM];
__device__ __align__(256) uint8_t g_QT8h [(size_t)DDIM * DDIM];
__device__ __align__(256) uint8_t g_QT8l [(size_t)DDIM * DDIM];
__device__ float g_cs[DDIM];

// ---------------------------------------------------------------------------
// PTX helpers (sm_80/sm_89 standard features only)
// ---------------------------------------------------------------------------
__device__ __forceinline__ uint32_t smem_u32(const void* p) {
    uint32_t a;
    asm("{ .reg .u64 t; cvta.to.shared.u64 t, %1; cvt.u32.u64 %0, t; }" : "=r"(a) : "l"(p));
    return a;
}
__device__ __forceinline__ void cp_async16(uint32_t dst, const void* src) {
    asm volatile("cp.async.cg.shared.global [%0], [%1], 16;" :: "r"(dst), "l"(src));
}
__device__ __forceinline__ void cp_commit() { asm volatile("cp.async.commit_group;" ::: "memory"); }
template <int N>
__device__ __forceinline__ void cp_wait() { asm volatile("cp.async.wait_group %0;" :: "n"(N) : "memory"); }

#define LDSM_X4(r0, r1, r2, r3, addr) \
    asm volatile("ldmatrix.sync.aligned.m8n8.x4.shared.b16 {%0,%1,%2,%3}, [%4];" \
        : "=r"(r0), "=r"(r1), "=r"(r2), "=r"(r3) : "r"(addr))

__device__ __forceinline__ void mma_bf16(float* c, const uint32_t* a, const uint32_t* b) {
    asm volatile(
        "mma.sync.aligned.m16n8k16.row.col.f32.bf16.bf16.f32 "
        "{%0,%1,%2,%3}, {%4,%5,%6,%7}, {%8,%9}, {%0,%1,%2,%3};"
        : "+f"(c[0]), "+f"(c[1]), "+f"(c[2]), "+f"(c[3])
        : "r"(a[0]), "r"(a[1]), "r"(a[2]), "r"(a[3]), "r"(b[0]), "r"(b[1]));
}
__device__ __forceinline__ void mma_fp8(float* c, const uint32_t* a, const uint32_t* b) {
    asm volatile(
        "mma.sync.aligned.m16n8k32.row.col.f32.e4m3.e4m3.f32 "
        "{%0,%1,%2,%3}, {%4,%5,%6,%7}, {%8,%9}, {%0,%1,%2,%3};"
        : "+f"(c[0]), "+f"(c[1]), "+f"(c[2]), "+f"(c[3])
        : "r"(a[0]), "r"(a[1]), "r"(a[2]), "r"(a[3]), "r"(b[0]), "r"(b[1]));
}
// returns (e4m3(vhigh) << 8) | e4m3(vlow)
__device__ __forceinline__ uint16_t pack_e4m3(float vhigh, float vlow) {
    uint16_t r;
    asm("cvt.rn.satfinite.e4m3x2.f32 %0, %1, %2;" : "=h"(r) : "f"(vhigh), "f"(vlow));
    return r;
}

// ---------------------------------------------------------------------------
// Prep: fused mag + colscale
// ---------------------------------------------------------------------------
__global__ void magcol_kernel(const float* __restrict__ magnitude,
                              const float* __restrict__ direction) {
    int o = blockIdx.x;
    const float* row = direction + (size_t)o * DDIM;
    float sm = 0.0f, sd = 0.0f;
    for (int i = threadIdx.x; i < DDIM; i += 256) {
        float a = magnitude[i];  sm += a * a;
        float b = row[i];        sd += b * b;
    }
    __shared__ float rm[256], rd[256];
    rm[threadIdx.x] = sm; rd[threadIdx.x] = sd;
    __syncthreads();
    for (int off = 128; off > 0; off >>= 1) {
        if (threadIdx.x < off) {
            rm[threadIdx.x] += rm[threadIdx.x + off];
            rd[threadIdx.x] += rd[threadIdx.x + off];
        }
        __syncthreads();
    }
    if (threadIdx.x == 0)
        g_cs[o] = sqrtf(rm[0]) * SCALING_F / fmaxf(sqrtf(rd[0]), EPS_F);
}

// ---------------------------------------------------------------------------
// Prep: split to (bf16 hi, fp8 hi*s, fp8 lo*s*2^9); 8 elems/thread
// ---------------------------------------------------------------------------
__device__ __forceinline__ void split8(const float* __restrict__ in, bf16* __restrict__ hi,
                                       uint8_t* __restrict__ h8, uint8_t* __restrict__ l8,
                                       int i, float s) {
    float4 a = ((const float4*)in)[i * 2];
    float4 b = ((const float4*)in)[i * 2 + 1];
    float v[8] = {a.x, a.y, a.z, a.w, b.x, b.y, b.z, b.w};
    uint32_t hw[4];
    float hf[8], lf[8];
    #pragma unroll
    for (int q = 0; q < 4; q++) {
        bf16 h0 = __float2bfloat16(v[q * 2]);
        bf16 h1 = __float2bfloat16(v[q * 2 + 1]);
        hf[q * 2] = __bfloat162float(h0);
        hf[q * 2 + 1] = __bfloat162float(h1);
        lf[q * 2] = v[q * 2] - hf[q * 2];
        lf[q * 2 + 1] = v[q * 2 + 1] - hf[q * 2 + 1];
        __nv_bfloat162 hp; hp.x = h0; hp.y = h1;
        hw[q] = *(uint32_t*)&hp;
    }
    uint4 hv; hv.x = hw[0]; hv.y = hw[1]; hv.z = hw[2]; hv.w = hw[3];
    ((uint4*)hi)[i] = hv;
    const float sl = s * S_LO;
    uint32_t p0 = (uint32_t)pack_e4m3(hf[1] * s, hf[0] * s)
                | ((uint32_t)pack_e4m3(hf[3] * s, hf[2] * s) << 16);
    uint32_t p1 = (uint32_t)pack_e4m3(hf[5] * s, hf[4] * s)
                | ((uint32_t)pack_e4m3(hf[7] * s, hf[6] * s) << 16);
    ((uint2*)h8)[i] = make_uint2(p0, p1);
    uint32_t q0 = (uint32_t)pack_e4m3(lf[1] * sl, lf[0] * sl)
                | ((uint32_t)pack_e4m3(lf[3] * sl, lf[2] * sl) << 16);
    uint32_t q1 = (uint32_t)pack_e4m3(lf[5] * sl, lf[4] * sl)
                | ((uint32_t)pack_e4m3(lf[7] * sl, lf[6] * sl) << 16);
    ((uint2*)l8)[i] = make_uint2(q0, q1);
}

#define NX8 ((NTOK * DDIM) / 8)
#define ND8 ((DDIM * DDIM) / 8)
#define BX  (NX8 / 256)
#define BD  (ND8 / 256)

__global__ void fused_split(const float* __restrict__ x,
                            const float* __restrict__ lB,
                            const float* __restrict__ dir) {
    int b = blockIdx.x;
    if (b < BX) {
        split8(x, g_x_hi, g_x8h, g_x8l, b * 256 + threadIdx.x, SX);
    } else if (b < BX + BD) {
        split8(lB, g_lB_hi, g_lB8h, g_lB8l, (b - BX) * 256 + threadIdx.x, SW);
    } else {
        split8(dir, g_dir_hi, g_dir8h, g_dir8l, (b - BX - BD) * 256 + threadIdx.x, SW);
    }
}

__global__ void transpose_split(const float* __restrict__ in) {
    __shared__ float t[32][33];
    int bx = blockIdx.x * 32, by = blockIdx.y * 32;
    int tx = threadIdx.x, ty = threadIdx.y;  // 32 x 8
    #pragma unroll
    for (int j = 0; j < 32; j += 8)
        t[ty + j][tx] = in[(size_t)(by + ty + j) * DDIM + bx + tx];
    __syncthreads();
    #pragma unroll
    for (int j = 0; j < 32; j += 8) {
        float v = t[tx][ty + j];
        size_t o = (size_t)(bx + ty + j) * DDIM + by + tx;
        bf16 h = __float2bfloat16(v);
        float hf = __bfloat162float(h);
        g_lAT_hi[o] = h;
        g_lAT8h[o] = (uint8_t)(pack_e4m3(0.0f, hf * SW) & 0xFF);
        g_lAT8l[o] = (uint8_t)(pack_e4m3(0.0f, (v - hf) * SW * S_LO) & 0xFF);
    }
}

// ---------------------------------------------------------------------------
// GEMM: C[M,N] = A[M,K] * B[N,K]^T, K=2048, CTA tile 128x128.
// Phase A: fp8 cross terms (A8h*B8l + A8l*B8h), BK=128, acc *= crossInv.
// Phase B: bf16 hh (Ahi*Bhi), BK=128, accumulate on top.
// EPI 0: fp32 out.  EPI 1: split out (hi bf16 + fp8 h/l, scale outS).
// EPI 2: like 1 with rowscale[m] first.
// ---------------------------------------------------------------------------
template <int EPI>
__global__ __launch_bounds__(256, 1)
void gemm_split(const bf16* __restrict__ Ahi_g, const uint8_t* __restrict__ A8h_g,
                const uint8_t* __restrict__ A8l_g,
                const bf16* __restrict__ Bhi_g, const uint8_t* __restrict__ B8h_g,
                const uint8_t* __restrict__ B8l_g,
                float* __restrict__ Cf, bf16* __restrict__ Chi,
                uint8_t* __restrict__ C8h, uint8_t* __restrict__ C8l,
                const float* __restrict__ rowscale, float crossInv, float outS)
{
    extern __shared__ __align__(128) char smem[];
    const uint32_t sb = smem_u32(smem);

    constexpr int K = KDIM;
    constexpr int BK = 128, NC = K / BK, S = 3;
    constexpr uint32_t T8 = 128 * 128;          // fp8 tile: 16 KB
    constexpr uint32_t ST8 = 4 * T8;            // 64 KB / stage (A8h,A8l,B8h,B8l)
    constexpr uint32_t TB = 128 * 256;          // bf16 tile: 32 KB
    constexpr uint32_t STB = 2 * TB;            // 64 KB / stage (Ahi,Bhi)

    const int tid = threadIdx.x;
    const int m0 = blockIdx.y * 128;
    const int n0 = blockIdx.x * 128;
    const int ldc = gridDim.x * 128;
    const int wid = tid >> 5, lane = tid & 31;
    const int wm = (wid >> 2) * 64;
    const int wn = (wid & 3) * 32;

    // ldmatrix lane components (shared by both phases)
    const int a_row_l = lane & 15;
    const int a_kb_l  = (lane >> 4) * 16;
    const int b_n_l   = (lane & 7) + ((lane >> 4) << 3);
    const int b_kb_l  = ((lane >> 3) & 1) * 16;

    float acc[4][4][4];
    #pragma unroll
    for (int a = 0; a < 4; a++)
        #pragma unroll
        for (int b = 0; b < 4; b++)
            #pragma unroll
            for (int q = 0; q < 4; q++) acc[a][b][q] = 0.0f;

    // ======================= Phase A: fp8 cross terms ======================
    {
        const int lrow = tid >> 3;        // 0..31
        const int lg   = tid & 7;         // 16B group in 128B row
        const uint8_t* pa_h = A8h_g + (size_t)m0 * K;
        const uint8_t* pa_l = A8l_g + (size_t)m0 * K;
        const uint8_t* pb_h = B8h_g + (size_t)n0 * K;
        const uint8_t* pb_l = B8l_g + (size_t)n0 * K;

        auto load8 = [&](int slot, int c) {
            const uint32_t base = sb + (uint32_t)slot * ST8;
            const int k0 = c * BK + lg * 16;
            #pragma unroll
            for (int t = 0; t < 4; t++) {
                const uint8_t* bp = (t == 0) ? pa_h : (t == 1) ? pa_l : (t == 2) ? pb_h : pb_l;
                #pragma unroll
                for (int j = 0; j < 4; j++) {
                    const int row = lrow + 32 * j;
                    uint32_t off = (uint32_t)row * 128
                                 + (((uint32_t)lg * 16) ^ (((uint32_t)row & 7) << 4));
                    cp_async16(base + (uint32_t)t * T8 + off, bp + (size_t)row * K + k0);
                }
            }
            cp_commit();
        };

        load8(0, 0);
        load8(1, 1);

        for (int c = 0; c < NC; c++) {
            if (c + 1 < NC) cp_wait<1>(); else cp_wait<0>();
            __syncthreads();
            if (c + 2 < NC) load8((c + 2) % S, c + 2);

            const uint32_t stg = sb + (uint32_t)(c % S) * ST8;
            const uint32_t Ah8 = stg, Al8 = stg + T8;
            const uint32_t Bh8 = stg + 2 * T8, Bl8 = stg + 3 * T8;

            #pragma unroll
            for (int s = 0; s < 4; s++) {          // 4 k32 steps per 128-chunk
                const int kb = s * 32;
                uint32_t a8h[4][4], a8l[4][4], b8h[4][2], b8l[4][2];
                #pragma unroll
                for (int mi = 0; mi < 4; mi++) {
                    const int row = wm + mi * 16 + a_row_l;
                    const uint32_t off = (uint32_t)row * 128
                        + (((uint32_t)(kb + a_kb_l)) ^ (((uint32_t)row & 7) << 4));
                    LDSM_X4(a8h[mi][0], a8h[mi][1], a8h[mi][2], a8h[mi][3], Ah8 + off);
                    LDSM_X4(a8l[mi][0], a8l[mi][1], a8l[mi][2], a8l[mi][3], Al8 + off);
                }
                #pragma unroll
                for (int nj2 = 0; nj2 < 2; nj2++) {
                    const int nr = wn + nj2 * 16 + b_n_l;
                    const uint32_t off = (uint32_t)nr * 128
                        + (((uint32_t)(kb + b_kb_l)) ^ (((uint32_t)nr & 7) << 4));
                    LDSM_X4(b8h[2*nj2][0], b8h[2*nj2][1], b8h[2*nj2+1][0], b8h[2*nj2+1][1],
                            Bh8 + off);
                    LDSM_X4(b8l[2*nj2][0], b8l[2*nj2][1], b8l[2*nj2+1][0], b8l[2*nj2+1][1],
                            Bl8 + off);
                }
                #pragma unroll
                for (int mi = 0; mi < 4; mi++)
                    #pragma unroll
                    for (int nj = 0; nj < 4; nj++)
                        mma_fp8(acc[mi][nj], a8h[mi], b8l[nj]);
                #pragma unroll
                for (int mi = 0; mi < 4; mi++)
                    #pragma unroll
                    for (int nj = 0; nj < 4; nj++)
                        mma_fp8(acc[mi][nj], a8l[mi], b8h[nj]);
            }
        }

        // rescale cross contribution
        #pragma unroll
        for (int a = 0; a < 4; a++)
            #pragma unroll
            for (int b = 0; b < 4; b++)
                #pragma unroll
                for (int q = 0; q < 4; q++) acc[a][b][q] *= crossInv;
    }

    __syncthreads();   // smem reuse barrier between phases

    // ======================= Phase B: bf16 hh ==============================
    {
        const int lrow = tid >> 4;        // 0..15
        const int lg   = tid & 15;        // 16B group in 256B row
        const bf16* pa = Ahi_g + (size_t)m0 * K;
        const bf16* pb = Bhi_g + (size_t)n0 * K;

        auto loadB = [&](int slot, int c) {
            const uint32_t base = sb + (uint32_t)slot * STB;
            const int k0 = c * BK + lg * 8;   // elements
            #pragma unroll
            for (int t = 0; t < 2; t++) {
                const bf16* bp = (t == 0) ? pa : pb;
                #pragma unroll
                for (int j = 0; j < 8; j++) {
                    const int row = lrow + 16 * j;
                    uint32_t off = (uint32_t)row * 256
                                 + (((uint32_t)lg * 16) ^ (((uint32_t)row & 7) << 4));
                    cp_async16(base + (uint32_t)t * TB + off, bp + (size_t)row * K + k0);
                }
            }
            cp_commit();
        };

        loadB(0, 0);
        loadB(1, 1);

        uint32_t ah[2][4][4], bh[2][4][2];

        for (int c = 0; c < NC; c++) {
            if (c + 1 < NC) cp_wait<1>(); else cp_wait<0>();
            __syncthreads();
            if (c + 2 < NC) loadB((c + 2) % S, c + 2);

            const uint32_t stg = sb + (uint32_t)(c % S) * STB;
            const uint32_t As = stg, Bs = stg + TB;

            auto frags = [&](int buf, int s) {
                const int kb = s * 32;    // byte col within 256B row
                #pragma unroll
                for (int mi = 0; mi < 4; mi++) {
                    const int row = wm + mi * 16 + a_row_l;
                    const uint32_t off = (uint32_t)row * 256
                        + (((uint32_t)(kb + a_kb_l)) ^ (((uint32_t)row & 7) << 4));
                    LDSM_X4(ah[buf][mi][0], ah[buf][mi][1], ah[buf][mi][2], ah[buf][mi][3],
                            As + off);
                }
                #pragma unroll
                for (int nj2 = 0; nj2 < 2; nj2++) {
                    const int nr = wn + nj2 * 16 + b_n_l;
                    const uint32_t off = (uint32_t)nr * 256
                        + (((uint32_t)(kb + b_kb_l)) ^ (((uint32_t)nr & 7) << 4));
                    LDSM_X4(bh[buf][2*nj2][0], bh[buf][2*nj2][1],
                            bh[buf][2*nj2+1][0], bh[buf][2*nj2+1][1], Bs + off);
                }
            };

            frags(0, 0);
            #pragma unroll
            for (int s = 0; s < 8; s++) {     // 8 k16 steps per 128-chunk
                const int cur = s & 1;
                if (s < 7) frags(cur ^ 1, s + 1);
                #pragma unroll
                for (int mi = 0; mi < 4; mi++)
                    #pragma unroll
                    for (int nj = 0; nj < 4; nj++)
                        mma_bf16(acc[mi][nj], ah[cur][mi], bh[cur][nj]);
            }
        }
    }

    // ============================ epilogue =================================
    const int g  = lane >> 2;
    const int t4 = lane & 3;
    #pragma unroll
    for (int mi = 0; mi < 4; mi++) {
        const int r0 = m0 + wm + mi * 16 + g;
        const int r1 = r0 + 8;
        float rs0 = 1.0f, rs1 = 1.0f;
        if (EPI == 2) { rs0 = rowscale[r0]; rs1 = rowscale[r1]; }
        #pragma unroll
        for (int nj = 0; nj < 4; nj++) {
            const int col = n0 + wn + nj * 8 + t4 * 2;
            float c0 = acc[mi][nj][0], c1 = acc[mi][nj][1];
            float c2 = acc[mi][nj][2], c3 = acc[mi][nj][3];
            if (EPI == 0) {
                float2 v0; v0.x = c0; v0.y = c1;
                float2 v1; v1.x = c2; v1.y = c3;
                *(float2*)(Cf + (size_t)r0 * ldc + col) = v0;
                *(float2*)(Cf + (size_t)r1 * ldc + col) = v1;
            } else {
                c0 *= rs0; c1 *= rs0; c2 *= rs1; c3 *= rs1;
                bf16 h0 = __float2bfloat16(c0), h1 = __float2bfloat16(c1);
                bf16 h2 = __float2bfloat16(c2), h3 = __float2bfloat16(c3);
                float hf0 = __bfloat162float(h0), hf1 = __bfloat162float(h1);
                float hf2 = __bfloat162float(h2), hf3 = __bfloat162float(h3);
                __nv_bfloat162 hp0; hp0.x = h0; hp0.y = h1;
                __nv_bfloat162 hp1; hp1.x = h2; hp1.y = h3;
                *(__nv_bfloat162*)(Chi + (size_t)r0 * ldc + col) = hp0;
                *(__nv_bfloat162*)(Chi + (size_t)r1 * ldc + col) = hp1;
                const float sl = outS * S_LO;
                *(uint16_t*)(C8h + (size_t)r0 * ldc + col) = pack_e4m3(hf1 * outS, hf0 * outS);
                *(uint16_t*)(C8h + (size_t)r1 * ldc + col) = pack_e4m3(hf3 * outS, hf2 * outS);
                *(uint16_t*)(C8l + (size_t)r0 * ldc + col) =
                    pack_e4m3((c1 - hf1) * sl, (c0 - hf0) * sl);
                *(uint16_t*)(C8l + (size_t)r1 * ldc + col) =
                    pack_e4m3((c3 - hf3) * sl, (c2 - hf2) * sl);
            }
        }
    }
}

// ---------------------------------------------------------------------------
// Launch
// ---------------------------------------------------------------------------
static constexpr int GEMM_SMEM = 3 * 64 * 1024;  // 196608 bytes

extern "C" void kernel_launch(void* const* d_in, const int* in_sizes, int n_in,
                              void* d_out, int out_size) {
    const float* x         = (const float*)d_in[0];
    const float* lora_A    = (const float*)d_in[1];
    const float* lora_B    = (const float*)d_in[2];
    const float* magnitude = (const float*)d_in[3];
    const float* direction = (const float*)d_in[4];
    float* out = (float*)d_out;

    bf16 *x_hi, *lB_hi, *lAT_hi, *dir_hi, *P_hi, *QT_hi;
    uint8_t *x8h, *x8l, *lB8h, *lB8l, *lAT8h, *lAT8l, *dir8h, *dir8l;
    uint8_t *P8h, *P8l, *QT8h, *QT8l;
    float* cs;
    cudaGetSymbolAddress((void**)&x_hi, g_x_hi);
    cudaGetSymbolAddress((void**)&x8h, g_x8h);   cudaGetSymbolAddress((void**)&x8l, g_x8l);
    cudaGetSymbolAddress((void**)&lB_hi, g_lB_hi);
    cudaGetSymbolAddress((void**)&lB8h, g_lB8h); cudaGetSymbolAddress((void**)&lB8l, g_lB8l);
    cudaGetSymbolAddress((void**)&lAT_hi, g_lAT_hi);
    cudaGetSymbolAddress((void**)&lAT8h, g_lAT8h); cudaGetSymbolAddress((void**)&lAT8l, g_lAT8l);
    cudaGetSymbolAddress((void**)&dir_hi, g_dir_hi);
    cudaGetSymbolAddress((void**)&dir8h, g_dir8h); cudaGetSymbolAddress((void**)&dir8l, g_dir8l);
    cudaGetSymbolAddress((void**)&P_hi, g_P_hi);
    cudaGetSymbolAddress((void**)&P8h, g_P8h);   cudaGetSymbolAddress((void**)&P8l, g_P8l);
    cudaGetSymbolAddress((void**)&QT_hi, g_QT_hi);
    cudaGetSymbolAddress((void**)&QT8h, g_QT8h); cudaGetSymbolAddress((void**)&QT8l, g_QT8l);
    cudaGetSymbolAddress((void**)&cs, g_cs);

    cudaFuncSetAttribute(gemm_split<0>, cudaFuncAttributeMaxDynamicSharedMemorySize, GEMM_SMEM);
    cudaFuncSetAttribute(gemm_split<1>, cudaFuncAttributeMaxDynamicSharedMemorySize, GEMM_SMEM);
    cudaFuncSetAttribute(gemm_split<2>, cudaFuncAttributeMaxDynamicSharedMemorySize, GEMM_SMEM);

    // 1: fused split of x, lora_B, direction
    fused_split<<<BX + 2 * BD, 256>>>(x, lora_B, direction);
    // 2: transpose+split lora_A -> lAT
    dim3 tgrid(DDIM / 32, DDIM / 32), tblk(32, 8);
    transpose_split<<<tgrid, tblk>>>(lora_A);
    // 3: fused mag + colscale
    magcol_kernel<<<DDIM, 256>>>(magnitude, direction);

    // crossInv = 1 / (sA * sB * 2^9)
    const float inv1 = 1.0f / (SW * SW * S_LO);
    const float inv2 = 1.0f / (SW * SP * S_LO);
    const float inv3 = 1.0f / (SX * SQT * S_LO);

    // 4: P[o,i] = lora_B[o,:] . lAT[i,:]
    dim3 gs(DDIM / 128, DDIM / 128);
    gemm_split<1><<<gs, 256, GEMM_SMEM>>>(lB_hi, lB8h, lB8l, lAT_hi, lAT8h, lAT8l,
                                          nullptr, P_hi, P8h, P8l, nullptr, inv1, SP);
    // 5: QT[oo,o] = cs[oo] * (dir[oo,:] . P[o,:])
    gemm_split<2><<<gs, 256, GEMM_SMEM>>>(dir_hi, dir8h, dir8l, P_hi, P8h, P8l,
                                          nullptr, QT_hi, QT8h, QT8l, cs, inv2, SQT);
    // 6: out[n,oo] = x[n,:] . QT[oo,:]
    dim3 gb(DDIM / 128, NTOK / 128);
    gemm_split<0><<<gb, 256, GEMM_SMEM>>>(x_hi, x8h, x8l, QT_hi, QT8h, QT8l,
                                          out, nullptr, nullptr, nullptr, nullptr, inv3, 1.0f);
}

// round 9
// speedup vs baseline: 1.0585x; 1.0585x over previous
#include <cuda_runtime.h>
#include <cuda_bf16.h>
#include <cstdint>
#include <math.h>

typedef __nv_bfloat16 bf16;

#define NTOK 8192
#define DDIM 2048
#define KDIM 2048
#define SCALING_F (16.0f / 2048.0f)
#define EPS_F 1e-12f

// ---------------------------------------------------------------------------
// Static device scratch
// ---------------------------------------------------------------------------
__device__ bf16 g_x_hi [(size_t)NTOK * DDIM];
__device__ bf16 g_x_lo [(size_t)NTOK * DDIM];
__device__ bf16 g_lA_hi[(size_t)DDIM * DDIM];
__device__ bf16 g_lA_lo[(size_t)DDIM * DDIM];
__device__ bf16 g_lB_hi[(size_t)DDIM * DDIM];
__device__ bf16 g_lB_lo[(size_t)DDIM * DDIM];
__device__ bf16 g_dir_hi[(size_t)DDIM * DDIM];
__device__ bf16 g_dir_lo[(size_t)DDIM * DDIM];
__device__ bf16 g_T1_hi[(size_t)DDIM * DDIM];   // T1 = dir @ lora_A^T  [oo, r]
__device__ bf16 g_T1_lo[(size_t)DDIM * DDIM];
__device__ bf16 g_QT_hi[(size_t)DDIM * DDIM];   // QT[oo,o] = cs[oo]*(T1 @ lora_B^T)
__device__ bf16 g_QT_lo[(size_t)DDIM * DDIM];
__device__ float g_cs[DDIM];

// ---------------------------------------------------------------------------
// PTX helpers — standard features only (sm_80+)
// ---------------------------------------------------------------------------
__device__ __forceinline__ uint32_t smem_u32(const void* p) {
    uint32_t a;
    asm("{ .reg .u64 t; cvta.to.shared.u64 t, %1; cvt.u32.u64 %0, t; }" : "=r"(a) : "l"(p));
    return a;
}
__device__ __forceinline__ void cp_async16(uint32_t dst, const void* src) {
    asm volatile("cp.async.cg.shared.global [%0], [%1], 16;" :: "r"(dst), "l"(src));
}
__device__ __forceinline__ void cp_commit() { asm volatile("cp.async.commit_group;" ::: "memory"); }
template <int N>
__device__ __forceinline__ void cp_wait() { asm volatile("cp.async.wait_group %0;" :: "n"(N) : "memory"); }

#define LDSM_X4(r0, r1, r2, r3, addr) \
    asm volatile("ldmatrix.sync.aligned.m8n8.x4.shared.b16 {%0,%1,%2,%3}, [%4];" \
        : "=r"(r0), "=r"(r1), "=r"(r2), "=r"(r3) : "r"(addr))

__device__ __forceinline__ void mma_bf16(float* c, const uint32_t* a, const uint32_t* b) {
    asm volatile(
        "mma.sync.aligned.m16n8k16.row.col.f32.bf16.bf16.f32 "
        "{%0,%1,%2,%3}, {%4,%5,%6,%7}, {%8,%9}, {%0,%1,%2,%3};"
        : "+f"(c[0]), "+f"(c[1]), "+f"(c[2]), "+f"(c[3])
        : "r"(a[0]), "r"(a[1]), "r"(a[2]), "r"(a[3]), "r"(b[0]), "r"(b[1]));
}

// ---------------------------------------------------------------------------
// Prep: fused mag + colscale
// ---------------------------------------------------------------------------
__global__ void magcol_kernel(const float* __restrict__ magnitude,
                              const float* __restrict__ direction) {
    int o = blockIdx.x;
    const float* row = direction + (size_t)o * DDIM;
    float sm = 0.0f, sd = 0.0f;
    for (int i = threadIdx.x; i < DDIM; i += 256) {
        float a = magnitude[i];  sm += a * a;
        float b = row[i];        sd += b * b;
    }
    __shared__ float rm[256], rd[256];
    rm[threadIdx.x] = sm; rd[threadIdx.x] = sd;
    __syncthreads();
    for (int off = 128; off > 0; off >>= 1) {
        if (threadIdx.x < off) {
            rm[threadIdx.x] += rm[threadIdx.x + off];
            rd[threadIdx.x] += rd[threadIdx.x + off];
        }
        __syncthreads();
    }
    if (threadIdx.x == 0)
        g_cs[o] = sqrtf(rm[0]) * SCALING_F / fmaxf(sqrtf(rd[0]), EPS_F);
}

// ---------------------------------------------------------------------------
// Prep: fused split of x, lora_A, lora_B, direction (8 floats/thread)
// (chain reorder removed the need for any transpose)
// ---------------------------------------------------------------------------
__device__ __forceinline__ void split8(const float* __restrict__ in,
                                       bf16* __restrict__ hi, bf16* __restrict__ lo,
                                       int i) {
    float4 a = ((const float4*)in)[i * 2];
    float4 b = ((const float4*)in)[i * 2 + 1];
    float v[8] = {a.x, a.y, a.z, a.w, b.x, b.y, b.z, b.w};
    uint32_t hw[4], lw[4];
    #pragma unroll
    for (int q = 0; q < 4; q++) {
        bf16 h0 = __float2bfloat16(v[q * 2]);
        bf16 h1 = __float2bfloat16(v[q * 2 + 1]);
        __nv_bfloat162 hp; hp.x = h0; hp.y = h1;
        hw[q] = *(uint32_t*)&hp;
        __nv_bfloat162 lp;
        lp.x = __float2bfloat16(v[q * 2] - __bfloat162float(h0));
        lp.y = __float2bfloat16(v[q * 2 + 1] - __bfloat162float(h1));
        lw[q] = *(uint32_t*)&lp;
    }
    uint4 hv; hv.x = hw[0]; hv.y = hw[1]; hv.z = hw[2]; hv.w = hw[3];
    uint4 lv; lv.x = lw[0]; lv.y = lw[1]; lv.z = lw[2]; lv.w = lw[3];
    ((uint4*)hi)[i] = hv;
    ((uint4*)lo)[i] = lv;
}

#define NX8 ((NTOK * DDIM) / 8)
#define ND8 ((DDIM * DDIM) / 8)
#define BX  (NX8 / 256)
#define BD  (ND8 / 256)

__global__ void fused_split(const float* __restrict__ x,
                            const float* __restrict__ lA,
                            const float* __restrict__ lB,
                            const float* __restrict__ dir) {
    int b = blockIdx.x;
    if (b < BX) {
        split8(x, g_x_hi, g_x_lo, b * 256 + threadIdx.x);
    } else if (b < BX + BD) {
        split8(lA, g_lA_hi, g_lA_lo, (b - BX) * 256 + threadIdx.x);
    } else if (b < BX + 2 * BD) {
        split8(lB, g_lB_hi, g_lB_lo, (b - BX - BD) * 256 + threadIdx.x);
    } else {
        split8(dir, g_dir_hi, g_dir_lo, (b - BX - 2 * BD) * 256 + threadIdx.x);
    }
}

// ---------------------------------------------------------------------------
// Split-bf16 GEMM: C[M,N] = A[M,K]*B[N,K]^T, K=2048.
// CTA tile 128x256, warp tile 64x64 (2x4 warp grid), BK=32, S=4 stages
// (stage 48KB: Ah 8K | Al 8K | Bh 16K | Bl 16K), 64B-row XOR swizzle
// (validated in R6). 3 sweeps hh/lh/hl with B-frag register reuse.
// EPI 0: fp32 out. EPI 1: split bf16 hi/lo. EPI 2: split + rowscale[m].
// ---------------------------------------------------------------------------
template <int EPI>
__global__ __launch_bounds__(256, 1)
void gemm_split(const bf16* __restrict__ Ah_g, const bf16* __restrict__ Al_g,
                const bf16* __restrict__ Bh_g, const bf16* __restrict__ Bl_g,
                float* __restrict__ Cf, bf16* __restrict__ Chi, bf16* __restrict__ Clo,
                const float* __restrict__ rowscale)
{
    extern __shared__ __align__(128) char smem[];
    const uint32_t sb = smem_u32(smem);

    constexpr int K = KDIM, BK = 32, NC = K / BK;
    constexpr uint32_t TA = 128 * 64;       // 8 KB  (A operand tile)
    constexpr uint32_t TB = 256 * 64;       // 16 KB (B operand tile)
    constexpr uint32_t STAGE = 2 * TA + 2 * TB;  // 48 KB
    constexpr uint32_t OFF_AH = 0, OFF_AL = TA, OFF_BH = 2 * TA, OFF_BL = 2 * TA + TB;

    const int tid = threadIdx.x;
    const int m0 = blockIdx.y * 128;
    const int n0 = blockIdx.x * 256;
    const int ldc = gridDim.x * 256;
    const int wid = tid >> 5, lane = tid & 31;
    const int wm = (wid >> 2) * 64;   // 0 / 64
    const int wn = (wid & 3) * 64;    // 0/64/128/192

    // loader mapping: 12 x 16B per thread per stage
    const int c16  = tid & 3;         // 16B group within 64B row
    const int lrow = tid >> 2;        // 0..63
    const bf16* gpA_h = Ah_g + (size_t)m0 * K;
    const bf16* gpA_l = Al_g + (size_t)m0 * K;
    const bf16* gpB_h = Bh_g + (size_t)n0 * K;
    const bf16* gpB_l = Bl_g + (size_t)n0 * K;

    auto load_stage = [&](int slot, int c) {
        const uint32_t base = sb + (uint32_t)slot * STAGE;
        const int k0 = c * BK + c16 * 8;
        #pragma unroll
        for (int j = 0; j < 2; j++) {     // A operands: 128 rows
            const int row = lrow + 64 * j;
            const uint32_t off = (uint32_t)row * 64
                               + ((uint32_t)(c16 ^ ((row >> 1) & 3))) * 16;
            cp_async16(base + OFF_AH + off, gpA_h + (size_t)row * K + k0);
            cp_async16(base + OFF_AL + off, gpA_l + (size_t)row * K + k0);
        }
        #pragma unroll
        for (int j = 0; j < 4; j++) {     // B operands: 256 rows
            const int row = lrow + 64 * j;
            const uint32_t off = (uint32_t)row * 64
                               + ((uint32_t)(c16 ^ ((row >> 1) & 3))) * 16;
            cp_async16(base + OFF_BH + off, gpB_h + (size_t)row * K + k0);
            cp_async16(base + OFF_BL + off, gpB_l + (size_t)row * K + k0);
        }
        cp_commit();
    };

    float acc[4][8][4];
    #pragma unroll
    for (int a = 0; a < 4; a++)
        #pragma unroll
        for (int b = 0; b < 8; b++)
            #pragma unroll
            for (int q = 0; q < 4; q++) acc[a][b][q] = 0.0f;

    load_stage(0, 0);
    load_stage(1, 1);
    load_stage(2, 2);

    // ldmatrix lane components
    const int a_row_l = lane & 15;
    const int a_c16_l = lane >> 4;                        // 0/1
    const int b_n_l   = (lane & 7) + ((lane >> 4) << 3);
    const int b_c16_l = (lane >> 3) & 1;

    for (int c = 0; c < NC; c++) {
        if (c < NC - 2) cp_wait<2>();
        else if (c == NC - 2) cp_wait<1>();
        else cp_wait<0>();
        __syncthreads();
        if (c + 3 < NC) load_stage((c + 3) & 3, c + 3);

        const uint32_t stg = sb + (uint32_t)(c & 3) * STAGE;
        const uint32_t As_h = stg + OFF_AH, As_l = stg + OFF_AL;
        const uint32_t Bs_h = stg + OFF_BH, Bs_l = stg + OFF_BL;

        #pragma unroll
        for (int s = 0; s < 2; s++) {            // 2 k16 steps per 32-chunk
            uint32_t ah[4][4], al[4][4];
            #pragma unroll
            for (int mi = 0; mi < 4; mi++) {
                const int row = wm + mi * 16 + a_row_l;
                const uint32_t pc = (uint32_t)((s * 2 + a_c16_l) ^ ((row >> 1) & 3));
                const uint32_t off = (uint32_t)row * 64 + pc * 16;
                LDSM_X4(ah[mi][0], ah[mi][1], ah[mi][2], ah[mi][3], As_h + off);
                LDSM_X4(al[mi][0], al[mi][1], al[mi][2], al[mi][3], As_l + off);
            }
            #pragma unroll
            for (int h = 0; h < 2; h++) {        // two 32-col halves of warp N
                uint32_t bb[4][2];
                #pragma unroll
                for (int nj2 = 0; nj2 < 2; nj2++) {
                    const int nr = wn + h * 32 + nj2 * 16 + b_n_l;
                    const uint32_t pc = (uint32_t)((s * 2 + b_c16_l) ^ ((nr >> 1) & 3));
                    const uint32_t off = (uint32_t)nr * 64 + pc * 16;
                    LDSM_X4(bb[2*nj2][0], bb[2*nj2][1], bb[2*nj2+1][0], bb[2*nj2+1][1],
                            Bs_h + off);
                }
                #pragma unroll
                for (int mi = 0; mi < 4; mi++)
                    #pragma unroll
                    for (int njl = 0; njl < 4; njl++)
                        mma_bf16(acc[mi][h * 4 + njl], ah[mi], bb[njl]);
                #pragma unroll
                for (int mi = 0; mi < 4; mi++)
                    #pragma unroll
                    for (int njl = 0; njl < 4; njl++)
                        mma_bf16(acc[mi][h * 4 + njl], al[mi], bb[njl]);
                #pragma unroll
                for (int nj2 = 0; nj2 < 2; nj2++) {   // reload bb <- B-lo
                    const int nr = wn + h * 32 + nj2 * 16 + b_n_l;
                    const uint32_t pc = (uint32_t)((s * 2 + b_c16_l) ^ ((nr >> 1) & 3));
                    const uint32_t off = (uint32_t)nr * 64 + pc * 16;
                    LDSM_X4(bb[2*nj2][0], bb[2*nj2][1], bb[2*nj2+1][0], bb[2*nj2+1][1],
                            Bs_l + off);
                }
                #pragma unroll
                for (int mi = 0; mi < 4; mi++)
                    #pragma unroll
                    for (int njl = 0; njl < 4; njl++)
                        mma_bf16(acc[mi][h * 4 + njl], ah[mi], bb[njl]);
            }
        }
    }

    // ---------------- epilogue ----------------
    const int g  = lane >> 2;
    const int t4 = lane & 3;
    #pragma unroll
    for (int mi = 0; mi < 4; mi++) {
        const int r0 = m0 + wm + mi * 16 + g;
        const int r1 = r0 + 8;
        float rs0 = 1.0f, rs1 = 1.0f;
        if (EPI == 2) { rs0 = rowscale[r0]; rs1 = rowscale[r1]; }
        #pragma unroll
        for (int nj = 0; nj < 8; nj++) {
            const int col = n0 + wn + nj * 8 + t4 * 2;
            float c0 = acc[mi][nj][0], c1 = acc[mi][nj][1];
            float c2 = acc[mi][nj][2], c3 = acc[mi][nj][3];
            if (EPI == 0) {
                float2 v0; v0.x = c0; v0.y = c1;
                float2 v1; v1.x = c2; v1.y = c3;
                *(float2*)(Cf + (size_t)r0 * ldc + col) = v0;
                *(float2*)(Cf + (size_t)r1 * ldc + col) = v1;
            } else {
                c0 *= rs0; c1 *= rs0; c2 *= rs1; c3 *= rs1;
                bf16 h0 = __float2bfloat16(c0), h1 = __float2bfloat16(c1);
                bf16 h2 = __float2bfloat16(c2), h3 = __float2bfloat16(c3);
                __nv_bfloat162 hp0; hp0.x = h0; hp0.y = h1;
                __nv_bfloat162 hp1; hp1.x = h2; hp1.y = h3;
                __nv_bfloat162 lp0, lp1;
                lp0.x = __float2bfloat16(c0 - __bfloat162float(h0));
                lp0.y = __float2bfloat16(c1 - __bfloat162float(h1));
                lp1.x = __float2bfloat16(c2 - __bfloat162float(h2));
                lp1.y = __float2bfloat16(c3 - __bfloat162float(h3));
                *(__nv_bfloat162*)(Chi + (size_t)r0 * ldc + col) = hp0;
                *(__nv_bfloat162*)(Chi + (size_t)r1 * ldc + col) = hp1;
                *(__nv_bfloat162*)(Clo + (size_t)r0 * ldc + col) = lp0;
                *(__nv_bfloat162*)(Clo + (size_t)r1 * ldc + col) = lp1;
            }
        }
    }
}

// ---------------------------------------------------------------------------
// Launch:  magcol(1) -> fused_split(2) -> gemm1(3) -> gemm2(4) -> gemm3(5)
// Chain:   T1 = dir @ lora_A^T ; QT = cs ⊙ (T1 @ lora_B^T) ; out = x @ QT^T
// ---------------------------------------------------------------------------
static constexpr int GEMM_SMEM = 4 * 48 * 1024;  // 196608 bytes

extern "C" void kernel_launch(void* const* d_in, const int* in_sizes, int n_in,
                              void* d_out, int out_size) {
    const float* x         = (const float*)d_in[0];
    const float* lora_A    = (const float*)d_in[1];
    const float* lora_B    = (const float*)d_in[2];
    const float* magnitude = (const float*)d_in[3];
    const float* direction = (const float*)d_in[4];
    float* out = (float*)d_out;

    bf16 *x_hi, *x_lo, *lA_hi, *lA_lo, *lB_hi, *lB_lo, *dir_hi, *dir_lo;
    bf16 *T1_hi, *T1_lo, *QT_hi, *QT_lo;
    float* cs;
    cudaGetSymbolAddress((void**)&x_hi, g_x_hi);   cudaGetSymbolAddress((void**)&x_lo, g_x_lo);
    cudaGetSymbolAddress((void**)&lA_hi, g_lA_hi); cudaGetSymbolAddress((void**)&lA_lo, g_lA_lo);
    cudaGetSymbolAddress((void**)&lB_hi, g_lB_hi); cudaGetSymbolAddress((void**)&lB_lo, g_lB_lo);
    cudaGetSymbolAddress((void**)&dir_hi, g_dir_hi); cudaGetSymbolAddress((void**)&dir_lo, g_dir_lo);
    cudaGetSymbolAddress((void**)&T1_hi, g_T1_hi); cudaGetSymbolAddress((void**)&T1_lo, g_T1_lo);
    cudaGetSymbolAddress((void**)&QT_hi, g_QT_hi); cudaGetSymbolAddress((void**)&QT_lo, g_QT_lo);
    cudaGetSymbolAddress((void**)&cs, g_cs);

    cudaFuncSetAttribute(gemm_split<0>, cudaFuncAttributeMaxDynamicSharedMemorySize, GEMM_SMEM);
    cudaFuncSetAttribute(gemm_split<1>, cudaFuncAttributeMaxDynamicSharedMemorySize, GEMM_SMEM);
    cudaFuncSetAttribute(gemm_split<2>, cudaFuncAttributeMaxDynamicSharedMemorySize, GEMM_SMEM);

    // 1: fused mag + colscale
    magcol_kernel<<<DDIM, 256>>>(magnitude, direction);
    // 2: fused split of all four fp32 tensors (no transpose needed)
    fused_split<<<BX + 3 * BD, 256>>>(x, lora_A, lora_B, direction);

    // 3: T1[oo,r] = sum_i dir[oo,i] * lora_A[r,i]    (split epilogue)
    dim3 gs(DDIM / 256, DDIM / 128);   // (8, 16) = 128 CTAs
    gemm_split<1><<<gs, 256, GEMM_SMEM>>>(dir_hi, dir_lo, lA_hi, lA_lo,
                                          nullptr, T1_hi, T1_lo, nullptr);
    // 4: QT[oo,o] = cs[oo] * sum_r T1[oo,r] * lora_B[o,r]   (split + rowscale)
    gemm_split<2><<<gs, 256, GEMM_SMEM>>>(T1_hi, T1_lo, lB_hi, lB_lo,
                                          nullptr, QT_hi, QT_lo, cs);
    // 5: out[n,oo] = sum_o x[n,o] * QT[oo,o]   (fp32 epilogue)
    dim3 gb(DDIM / 256, NTOK / 128);   // (8, 64) = 512 CTAs
    gemm_split<0><<<gb, 256, GEMM_SMEM>>>(x_hi, x_lo, QT_hi, QT_lo,
                                          out, nullptr, nullptr, nullptr);
}

// round 10
// speedup vs baseline: 2.0092x; 1.8982x over previous
#include <cuda_runtime.h>
#include <cuda_fp16.h>
#include <cstdint>
#include <math.h>

typedef __half f16;

#define NTOK 8192
#define DDIM 2048
#define KDIM 2048
#define SCALING_F (16.0f / 2048.0f)
#define EPS_F 1e-12f

// ---------------------------------------------------------------------------
// Static device scratch
// ---------------------------------------------------------------------------
__device__ f16 g_x16 [(size_t)NTOK * DDIM];     // x, plain fp16
__device__ f16 g_lAh [(size_t)DDIM * DDIM];     // lora_A split
__device__ f16 g_lAl [(size_t)DDIM * DDIM];
__device__ f16 g_lBh [(size_t)DDIM * DDIM];     // lora_B split
__device__ f16 g_lBl [(size_t)DDIM * DDIM];
__device__ f16 g_dsh [(size_t)DDIM * DDIM];     // (cs ⊙ direction) split
__device__ f16 g_dsl [(size_t)DDIM * DDIM];
__device__ f16 g_T1  [(size_t)DDIM * DDIM];     // T1 = (cs⊙dir) @ lora_A^T, plain fp16
__device__ f16 g_QT  [(size_t)DDIM * DDIM];     // QT = T1 @ lora_B^T, plain fp16
__device__ float g_cs[DDIM];

// ---------------------------------------------------------------------------
// PTX helpers — standard sm_80 features only
// ---------------------------------------------------------------------------
__device__ __forceinline__ uint32_t smem_u32(const void* p) {
    uint32_t a;
    asm("{ .reg .u64 t; cvta.to.shared.u64 t, %1; cvt.u32.u64 %0, t; }" : "=r"(a) : "l"(p));
    return a;
}
__device__ __forceinline__ void cp_async16(uint32_t dst, const void* src) {
    asm volatile("cp.async.cg.shared.global [%0], [%1], 16;" :: "r"(dst), "l"(src));
}
__device__ __forceinline__ void cp_commit() { asm volatile("cp.async.commit_group;" ::: "memory"); }
template <int N>
__device__ __forceinline__ void cp_wait() { asm volatile("cp.async.wait_group %0;" :: "n"(N) : "memory"); }

#define LDSM_X4(r0, r1, r2, r3, addr) \
    asm volatile("ldmatrix.sync.aligned.m8n8.x4.shared.b16 {%0,%1,%2,%3}, [%4];" \
        : "=r"(r0), "=r"(r1), "=r"(r2), "=r"(r3) : "r"(addr))

__device__ __forceinline__ void mma_f16(float* c, const uint32_t* a, const uint32_t* b) {
    asm volatile(
        "mma.sync.aligned.m16n8k16.row.col.f32.f16.f16.f32 "
        "{%0,%1,%2,%3}, {%4,%5,%6,%7}, {%8,%9}, {%0,%1,%2,%3};"
        : "+f"(c[0]), "+f"(c[1]), "+f"(c[2]), "+f"(c[3])
        : "r"(a[0]), "r"(a[1]), "r"(a[2]), "r"(a[3]), "r"(b[0]), "r"(b[1]));
}

// ---------------------------------------------------------------------------
// Prep 1: cs[o] = ||magnitude|| * SCALING / max(||direction[o,:]||, eps)
// ---------------------------------------------------------------------------
__global__ void magcol_kernel(const float* __restrict__ magnitude,
                              const float* __restrict__ direction) {
    int o = blockIdx.x;
    const float* row = direction + (size_t)o * DDIM;
    float sm = 0.0f, sd = 0.0f;
    for (int i = threadIdx.x; i < DDIM; i += 256) {
        float a = magnitude[i];  sm += a * a;
        float b = row[i];        sd += b * b;
    }
    __shared__ float rm[256], rd[256];
    rm[threadIdx.x] = sm; rd[threadIdx.x] = sd;
    __syncthreads();
    for (int off = 128; off > 0; off >>= 1) {
        if (threadIdx.x < off) {
            rm[threadIdx.x] += rm[threadIdx.x + off];
            rd[threadIdx.x] += rd[threadIdx.x + off];
        }
        __syncthreads();
    }
    if (threadIdx.x == 0)
        g_cs[o] = sqrtf(rm[0]) * SCALING_F / fmaxf(sqrtf(rd[0]), EPS_F);
}

// ---------------------------------------------------------------------------
// Prep 2: fused conversions (8 elems/thread, 16B stores)
//   x      -> plain fp16
//   lora_A -> fp16 hi/lo split
//   lora_B -> fp16 hi/lo split
//   dir    -> scaled by cs[row], fp16 hi/lo split
// ---------------------------------------------------------------------------
__device__ __forceinline__ void cvt8(const float* __restrict__ in, f16* __restrict__ out, int i) {
    float4 a = ((const float4*)in)[i * 2];
    float4 b = ((const float4*)in)[i * 2 + 1];
    __half2 h0 = __floats2half2_rn(a.x, a.y);
    __half2 h1 = __floats2half2_rn(a.z, a.w);
    __half2 h2 = __floats2half2_rn(b.x, b.y);
    __half2 h3 = __floats2half2_rn(b.z, b.w);
    uint4 v; v.x = *(uint32_t*)&h0; v.y = *(uint32_t*)&h1;
    v.z = *(uint32_t*)&h2; v.w = *(uint32_t*)&h3;
    ((uint4*)out)[i] = v;
}

__device__ __forceinline__ void split8h(const float* __restrict__ in, f16* __restrict__ hi,
                                        f16* __restrict__ lo, int i, float s) {
    float4 a = ((const float4*)in)[i * 2];
    float4 b = ((const float4*)in)[i * 2 + 1];
    float v[8] = {a.x * s, a.y * s, a.z * s, a.w * s, b.x * s, b.y * s, b.z * s, b.w * s};
    uint32_t hw[4], lw[4];
    #pragma unroll
    for (int q = 0; q < 4; q++) {
        f16 h0 = __float2half_rn(v[q * 2]);
        f16 h1 = __float2half_rn(v[q * 2 + 1]);
        __half2 hp; hp.x = h0; hp.y = h1;
        hw[q] = *(uint32_t*)&hp;
        __half2 lp;
        lp.x = __float2half_rn(v[q * 2] - __half2float(h0));
        lp.y = __float2half_rn(v[q * 2 + 1] - __half2float(h1));
        lw[q] = *(uint32_t*)&lp;
    }
    uint4 hv; hv.x = hw[0]; hv.y = hw[1]; hv.z = hw[2]; hv.w = hw[3];
    uint4 lv; lv.x = lw[0]; lv.y = lw[1]; lv.z = lw[2]; lv.w = lw[3];
    ((uint4*)hi)[i] = hv;
    ((uint4*)lo)[i] = lv;
}

#define NX8 ((NTOK * DDIM) / 8)
#define ND8 ((DDIM * DDIM) / 8)
#define BX  (NX8 / 256)
#define BD  (ND8 / 256)

__global__ void fused_prep(const float* __restrict__ x,
                           const float* __restrict__ lA,
                           const float* __restrict__ lB,
                           const float* __restrict__ dir) {
    int b = blockIdx.x;
    if (b < BX) {
        cvt8(x, g_x16, b * 256 + threadIdx.x);
    } else if (b < BX + BD) {
        split8h(lA, g_lAh, g_lAl, (b - BX) * 256 + threadIdx.x, 1.0f);
    } else if (b < BX + 2 * BD) {
        split8h(lB, g_lBh, g_lBl, (b - BX - BD) * 256 + threadIdx.x, 1.0f);
    } else {
        int i = (b - BX - 2 * BD) * 256 + threadIdx.x;
        int row = (i * 8) / DDIM;            // 8 | DDIM, so row constant per thread
        split8h(dir, g_dsh, g_dsl, i, g_cs[row]);
    }
}

// ---------------------------------------------------------------------------
// fp16 GEMM with variable pass count:  C[M,N] = A[M,K] * B[N,K]^T, K = 2048.
//   NPASS=3: A split (Ah,Al), B split (Bh,Bl): hh + hl + lh   (error ~u^2)
//   NPASS=2: A single (Ah),   B split (Bh,Bl): hh + hl        (error from A rounding)
//   NPASS=1: A single, B single: hh                           (error from both)
//   EPI=0: fp32 out.  EPI=1: plain fp16 out.
// CTA tile 128x128, BK=64, S=3 cp.async stages, proven SW128 XOR swizzle.
// ---------------------------------------------------------------------------
template <int NPASS, int EPI>
__global__ __launch_bounds__(256, 1)
void gemm_f16(const f16* __restrict__ Ah_g, const f16* __restrict__ Al_g,
              const f16* __restrict__ Bh_g, const f16* __restrict__ Bl_g,
              float* __restrict__ Cf, f16* __restrict__ Ch)
{
    extern __shared__ __align__(128) char smem[];
    const uint32_t sb = smem_u32(smem);

    constexpr int K = KDIM, BK = 64, NC = K / BK, S = 3;
    constexpr int NT = (NPASS == 3) ? 4 : (NPASS == 2) ? 3 : 2;  // tiles per stage
    constexpr uint32_t TILE = 128 * 128;       // 16 KB (128 rows x 128 B)
    constexpr uint32_t STAGE = (uint32_t)NT * TILE;
    // tile offsets within a stage:
    //   NPASS3: [Ah, Al, Bh, Bl]   NPASS2: [Ah, Bh, Bl]   NPASS1: [Ah, Bh]
    constexpr uint32_t OFF_AH = 0;
    constexpr uint32_t OFF_AL = (NPASS == 3) ? TILE : 0;            // unused if <3
    constexpr uint32_t OFF_BH = (NPASS == 3) ? 2 * TILE : TILE;
    constexpr uint32_t OFF_BL = (NPASS == 3) ? 3 * TILE : 2 * TILE; // unused if <2

    const int tid = threadIdx.x;
    const int m0 = blockIdx.y * 128;
    const int n0 = blockIdx.x * 128;
    const int ldc = gridDim.x * 128;
    const int wid = tid >> 5, lane = tid & 31;
    const int wm = (wid >> 2) * 64;
    const int wn = (wid & 3) * 32;

    const int lrow = tid >> 3;        // 0..31
    const int lg   = tid & 7;         // 16B group in 128B row
    const f16* gpAh = Ah_g + (size_t)m0 * K;
    const f16* gpAl = (NPASS == 3) ? Al_g + (size_t)m0 * K : nullptr;
    const f16* gpBh = Bh_g + (size_t)n0 * K;
    const f16* gpBl = (NPASS >= 2) ? Bl_g + (size_t)n0 * K : nullptr;

    auto load_tile = [&](uint32_t dstbase, const f16* bp, int k0) {
        #pragma unroll
        for (int j = 0; j < 4; j++) {
            const int row = lrow + 32 * j;
            uint32_t off = (uint32_t)row * 128 + (uint32_t)lg * 16;
            off ^= ((uint32_t)row & 7) << 4;
            cp_async16(dstbase + off, bp + (size_t)row * K + k0);
        }
    };
    auto load_stage = [&](int slot, int c) {
        const uint32_t base = sb + (uint32_t)slot * STAGE;
        const int k0 = c * BK + lg * 8;
        load_tile(base + OFF_AH, gpAh, k0);
        if (NPASS == 3) load_tile(base + OFF_AL, gpAl, k0);
        load_tile(base + OFF_BH, gpBh, k0);
        if (NPASS >= 2) load_tile(base + OFF_BL, gpBl, k0);
        cp_commit();
    };

    float acc[4][4][4];
    #pragma unroll
    for (int a = 0; a < 4; a++)
        #pragma unroll
        for (int b = 0; b < 4; b++)
            #pragma unroll
            for (int q = 0; q < 4; q++) acc[a][b][q] = 0.0f;

    load_stage(0, 0);
    load_stage(1, 1);

    // ldmatrix lane components
    const int a_row_l = lane & 15;
    const int a_kb_l  = (lane >> 4) * 16;
    const int b_n_l   = (lane & 7) + ((lane >> 4) << 3);
    const int b_kb_l  = ((lane >> 3) & 1) * 16;

    for (int c = 0; c < NC; c++) {
        if (c + 1 < NC) cp_wait<1>(); else cp_wait<0>();
        __syncthreads();
        if (c + 2 < NC) load_stage((c + 2) % S, c + 2);

        const uint32_t stg = sb + (uint32_t)(c % S) * STAGE;

        #pragma unroll
        for (int s = 0; s < 4; s++) {          // 4 k16 steps per 64-chunk
            const int kb = s * 32;
            uint32_t ah[4][4], al[4][4], bh[4][2], bl[4][2];
            #pragma unroll
            for (int mi = 0; mi < 4; mi++) {
                const int row = wm + mi * 16 + a_row_l;
                const uint32_t off = (uint32_t)row * 128
                    + (((uint32_t)(kb + a_kb_l)) ^ (((uint32_t)row & 7) << 4));
                LDSM_X4(ah[mi][0], ah[mi][1], ah[mi][2], ah[mi][3], stg + OFF_AH + off);
                if (NPASS == 3)
                    LDSM_X4(al[mi][0], al[mi][1], al[mi][2], al[mi][3], stg + OFF_AL + off);
            }
            #pragma unroll
            for (int nj2 = 0; nj2 < 2; nj2++) {
                const int nr = wn + nj2 * 16 + b_n_l;
                const uint32_t off = (uint32_t)nr * 128
                    + (((uint32_t)(kb + b_kb_l)) ^ (((uint32_t)nr & 7) << 4));
                LDSM_X4(bh[2*nj2][0], bh[2*nj2][1], bh[2*nj2+1][0], bh[2*nj2+1][1],
                        stg + OFF_BH + off);
                if (NPASS >= 2)
                    LDSM_X4(bl[2*nj2][0], bl[2*nj2][1], bl[2*nj2+1][0], bl[2*nj2+1][1],
                            stg + OFF_BL + off);
            }
            #pragma unroll
            for (int mi = 0; mi < 4; mi++)
                #pragma unroll
                for (int nj = 0; nj < 4; nj++)
                    mma_f16(acc[mi][nj], ah[mi], bh[nj]);
            if (NPASS >= 2) {
                #pragma unroll
                for (int mi = 0; mi < 4; mi++)
                    #pragma unroll
                    for (int nj = 0; nj < 4; nj++)
                        mma_f16(acc[mi][nj], ah[mi], bl[nj]);
            }
            if (NPASS == 3) {
                #pragma unroll
                for (int mi = 0; mi < 4; mi++)
                    #pragma unroll
                    for (int nj = 0; nj < 4; nj++)
                        mma_f16(acc[mi][nj], al[mi], bh[nj]);
            }
        }
    }

    // ---------------- epilogue ----------------
    const int g  = lane >> 2;
    const int t4 = lane & 3;
    #pragma unroll
    for (int mi = 0; mi < 4; mi++) {
        const int r0 = m0 + wm + mi * 16 + g;
        const int r1 = r0 + 8;
        #pragma unroll
        for (int nj = 0; nj < 4; nj++) {
            const int col = n0 + wn + nj * 8 + t4 * 2;
            float c0 = acc[mi][nj][0], c1 = acc[mi][nj][1];
            float c2 = acc[mi][nj][2], c3 = acc[mi][nj][3];
            if (EPI == 0) {
                float2 v0; v0.x = c0; v0.y = c1;
                float2 v1; v1.x = c2; v1.y = c3;
                *(float2*)(Cf + (size_t)r0 * ldc + col) = v0;
                *(float2*)(Cf + (size_t)r1 * ldc + col) = v1;
            } else {
                __half2 h0 = __floats2half2_rn(c0, c1);
                __half2 h1 = __floats2half2_rn(c2, c3);
                *(__half2*)(Ch + (size_t)r0 * ldc + col) = h0;
                *(__half2*)(Ch + (size_t)r1 * ldc + col) = h1;
            }
        }
    }
}

// ---------------------------------------------------------------------------
// Launch: magcol(1) -> fused_prep(2) -> gemm1(3) -> gemm2(4) -> gemm3(5)
// Chain:  T1 = (cs⊙dir) @ lora_A^T ;  QT = T1 @ lora_B^T ;  out = x @ QT^T
// ---------------------------------------------------------------------------
extern "C" void kernel_launch(void* const* d_in, const int* in_sizes, int n_in,
                              void* d_out, int out_size) {
    const float* x         = (const float*)d_in[0];
    const float* lora_A    = (const float*)d_in[1];
    const float* lora_B    = (const float*)d_in[2];
    const float* magnitude = (const float*)d_in[3];
    const float* direction = (const float*)d_in[4];
    float* out = (float*)d_out;

    f16 *x16, *lAh, *lAl, *lBh, *lBl, *dsh, *dsl, *T1, *QT;
    cudaGetSymbolAddress((void**)&x16, g_x16);
    cudaGetSymbolAddress((void**)&lAh, g_lAh); cudaGetSymbolAddress((void**)&lAl, g_lAl);
    cudaGetSymbolAddress((void**)&lBh, g_lBh); cudaGetSymbolAddress((void**)&lBl, g_lBl);
    cudaGetSymbolAddress((void**)&dsh, g_dsh); cudaGetSymbolAddress((void**)&dsl, g_dsl);
    cudaGetSymbolAddress((void**)&T1, g_T1);   cudaGetSymbolAddress((void**)&QT, g_QT);

    constexpr int SM3 = 4 * 128 * 128 * 3;   // 196608
    constexpr int SM2 = 3 * 128 * 128 * 3;   // 147456
    constexpr int SM1 = 2 * 128 * 128 * 3;   //  98304
    cudaFuncSetAttribute(gemm_f16<3, 1>, cudaFuncAttributeMaxDynamicSharedMemorySize, SM3);
    cudaFuncSetAttribute(gemm_f16<2, 1>, cudaFuncAttributeMaxDynamicSharedMemorySize, SM2);
    cudaFuncSetAttribute(gemm_f16<1, 0>, cudaFuncAttributeMaxDynamicSharedMemorySize, SM1);

    // 1: norms (must precede prep: dir is pre-scaled by cs)
    magcol_kernel<<<DDIM, 256>>>(magnitude, direction);
    // 2: fused conversions
    fused_prep<<<BX + 3 * BD, 256>>>(x, lora_A, lora_B, direction);

    dim3 gs(DDIM / 128, DDIM / 128);   // 16x16 = 256 CTAs
    dim3 gb(DDIM / 128, NTOK / 128);   // 16x64 = 1024 CTAs

    // 3: T1 = (cs⊙dir) @ lora_A^T   (3-pass, fp16 out)
    gemm_f16<3, 1><<<gs, 256, SM3>>>(dsh, dsl, lAh, lAl, nullptr, T1);
    // 4: QT = T1 @ lora_B^T          (2-pass: T1 single, lora_B split; fp16 out)
    gemm_f16<2, 1><<<gs, 256, SM2>>>(T1, nullptr, lBh, lBl, nullptr, QT);
    // 5: out = x @ QT^T              (1-pass; fp32 out)
    gemm_f16<1, 0><<<gb, 256, SM1>>>(x16, nullptr, QT, nullptr, out, nullptr);
}

// round 11
// speedup vs baseline: 2.6518x; 1.3199x over previous
#include <cuda_runtime.h>
#include <cuda_fp16.h>
#include <cstdint>
#include <math.h>

typedef __half f16;

#define NTOK 8192
#define DDIM 2048
#define KDIM 2048
#define SCALING_F (16.0f / 2048.0f)
#define EPS_F 1e-12f

// ---------------------------------------------------------------------------
// Static device scratch
// ---------------------------------------------------------------------------
__device__ f16 g_x16[(size_t)NTOK * DDIM];     // x
__device__ f16 g_lA [(size_t)DDIM * DDIM];     // lora_A
__device__ f16 g_lB [(size_t)DDIM * DDIM];     // lora_B
__device__ f16 g_ds [(size_t)DDIM * DDIM];     // cs ⊙ direction
__device__ f16 g_T1 [(size_t)DDIM * DDIM];     // T1 = (cs⊙dir) @ lora_A^T
__device__ f16 g_QT [(size_t)DDIM * DDIM];     // QT = T1 @ lora_B^T
__device__ float g_cs[DDIM];

// ---------------------------------------------------------------------------
// PTX helpers — standard sm_80 features only
// ---------------------------------------------------------------------------
__device__ __forceinline__ uint32_t smem_u32(const void* p) {
    uint32_t a;
    asm("{ .reg .u64 t; cvta.to.shared.u64 t, %1; cvt.u32.u64 %0, t; }" : "=r"(a) : "l"(p));
    return a;
}
__device__ __forceinline__ void cp_async16(uint32_t dst, const void* src) {
    asm volatile("cp.async.cg.shared.global [%0], [%1], 16;" :: "r"(dst), "l"(src));
}
__device__ __forceinline__ void cp_commit() { asm volatile("cp.async.commit_group;" ::: "memory"); }
template <int N>
__device__ __forceinline__ void cp_wait() { asm volatile("cp.async.wait_group %0;" :: "n"(N) : "memory"); }

#define LDSM_X4(r0, r1, r2, r3, addr) \
    asm volatile("ldmatrix.sync.aligned.m8n8.x4.shared.b16 {%0,%1,%2,%3}, [%4];" \
        : "=r"(r0), "=r"(r1), "=r"(r2), "=r"(r3) : "r"(addr))

__device__ __forceinline__ void mma_f16(float* c, const uint32_t* a, const uint32_t* b) {
    asm volatile(
        "mma.sync.aligned.m16n8k16.row.col.f32.f16.f16.f32 "
        "{%0,%1,%2,%3}, {%4,%5,%6,%7}, {%8,%9}, {%0,%1,%2,%3};"
        : "+f"(c[0]), "+f"(c[1]), "+f"(c[2]), "+f"(c[3])
        : "r"(a[0]), "r"(a[1]), "r"(a[2]), "r"(a[3]), "r"(b[0]), "r"(b[1]));
}

// ---------------------------------------------------------------------------
// Prep 1: cs[o] = ||magnitude|| * SCALING / max(||direction[o,:]||, eps)
// ---------------------------------------------------------------------------
__global__ void magcol_kernel(const float* __restrict__ magnitude,
                              const float* __restrict__ direction) {
    int o = blockIdx.x;
    const float* row = direction + (size_t)o * DDIM;
    float sm = 0.0f, sd = 0.0f;
    for (int i = threadIdx.x; i < DDIM; i += 256) {
        float a = magnitude[i];  sm += a * a;
        float b = row[i];        sd += b * b;
    }
    __shared__ float rm[256], rd[256];
    rm[threadIdx.x] = sm; rd[threadIdx.x] = sd;
    __syncthreads();
    for (int off = 128; off > 0; off >>= 1) {
        if (threadIdx.x < off) {
            rm[threadIdx.x] += rm[threadIdx.x + off];
            rd[threadIdx.x] += rd[threadIdx.x + off];
        }
        __syncthreads();
    }
    if (threadIdx.x == 0)
        g_cs[o] = sqrtf(rm[0]) * SCALING_F / fmaxf(sqrtf(rd[0]), EPS_F);
}

// ---------------------------------------------------------------------------
// Prep 2: fused fp32 -> fp16 conversions (8 elems/thread, 16B stores)
//   x, lora_A, lora_B plain; dir scaled by cs[row].
// ---------------------------------------------------------------------------
__device__ __forceinline__ void cvt8(const float* __restrict__ in, f16* __restrict__ out,
                                     int i, float s) {
    float4 a = ((const float4*)in)[i * 2];
    float4 b = ((const float4*)in)[i * 2 + 1];
    __half2 h0 = __floats2half2_rn(a.x * s, a.y * s);
    __half2 h1 = __floats2half2_rn(a.z * s, a.w * s);
    __half2 h2 = __floats2half2_rn(b.x * s, b.y * s);
    __half2 h3 = __floats2half2_rn(b.z * s, b.w * s);
    uint4 v; v.x = *(uint32_t*)&h0; v.y = *(uint32_t*)&h1;
    v.z = *(uint32_t*)&h2; v.w = *(uint32_t*)&h3;
    ((uint4*)out)[i] = v;
}

#define NX8 ((NTOK * DDIM) / 8)
#define ND8 ((DDIM * DDIM) / 8)
#define BX  (NX8 / 256)
#define BD  (ND8 / 256)

__global__ void fused_prep(const float* __restrict__ x,
                           const float* __restrict__ lA,
                           const float* __restrict__ lB,
                           const float* __restrict__ dir) {
    int b = blockIdx.x;
    if (b < BX) {
        cvt8(x, g_x16, b * 256 + threadIdx.x, 1.0f);
    } else if (b < BX + BD) {
        cvt8(lA, g_lA, (b - BX) * 256 + threadIdx.x, 1.0f);
    } else if (b < BX + 2 * BD) {
        cvt8(lB, g_lB, (b - BX - BD) * 256 + threadIdx.x, 1.0f);
    } else {
        int i = (b - BX - 2 * BD) * 256 + threadIdx.x;
        int row = (i * 8) / DDIM;        // 8 | DDIM -> row constant across the 8
        cvt8(dir, g_ds, i, g_cs[row]);
    }
}

// ---------------------------------------------------------------------------
// fp16 GEMM (single pass): C[M,N] = A[M,K] * B[N,K]^T, K = 2048.
// CTA tile 128x128, BK=64, S=3 cp.async stages, SW128 XOR swizzle (proven).
// EPI=0: fp32 out.  EPI=1: fp16 out.
// ---------------------------------------------------------------------------
template <int EPI>
__global__ __launch_bounds__(256, 1)
void gemm_f16(const f16* __restrict__ A_g, const f16* __restrict__ B_g,
              float* __restrict__ Cf, f16* __restrict__ Ch)
{
    extern __shared__ __align__(128) char smem[];
    const uint32_t sb = smem_u32(smem);

    constexpr int K = KDIM, BK = 64, NC = K / BK, S = 3;
    constexpr uint32_t TILE = 128 * 128;       // 16 KB
    constexpr uint32_t STAGE = 2 * TILE;       // A + B = 32 KB

    const int tid = threadIdx.x;
    const int m0 = blockIdx.y * 128;
    const int n0 = blockIdx.x * 128;
    const int ldc = gridDim.x * 128;
    const int wid = tid >> 5, lane = tid & 31;
    const int wm = (wid >> 2) * 64;
    const int wn = (wid & 3) * 32;

    const int lrow = tid >> 3;        // 0..31
    const int lg   = tid & 7;         // 16B group in 128B row
    const f16* gpA = A_g + (size_t)m0 * K;
    const f16* gpB = B_g + (size_t)n0 * K;

    auto load_stage = [&](int slot, int c) {
        const uint32_t base = sb + (uint32_t)slot * STAGE;
        const int k0 = c * BK + lg * 8;
        #pragma unroll
        for (int t = 0; t < 2; t++) {
            const f16* bp = (t == 0) ? gpA : gpB;
            #pragma unroll
            for (int j = 0; j < 4; j++) {
                const int row = lrow + 32 * j;
                uint32_t off = (uint32_t)row * 128 + (uint32_t)lg * 16;
                off ^= ((uint32_t)row & 7) << 4;
                cp_async16(base + (uint32_t)t * TILE + off, bp + (size_t)row * K + k0);
            }
        }
        cp_commit();
    };

    float acc[4][4][4];
    #pragma unroll
    for (int a = 0; a < 4; a++)
        #pragma unroll
        for (int b = 0; b < 4; b++)
            #pragma unroll
            for (int q = 0; q < 4; q++) acc[a][b][q] = 0.0f;

    load_stage(0, 0);
    load_stage(1, 1);

    // ldmatrix lane components
    const int a_row_l = lane & 15;
    const int a_kb_l  = (lane >> 4) * 16;
    const int b_n_l   = (lane & 7) + ((lane >> 4) << 3);
    const int b_kb_l  = ((lane >> 3) & 1) * 16;

    // double-buffered fragments
    uint32_t ah[2][4][4], bh[2][4][2];

    for (int c = 0; c < NC; c++) {
        if (c + 1 < NC) cp_wait<1>(); else cp_wait<0>();
        __syncthreads();
        if (c + 2 < NC) load_stage((c + 2) % S, c + 2);

        const uint32_t stg = sb + (uint32_t)(c % S) * STAGE;
        const uint32_t As = stg, Bs = stg + TILE;

        auto frags = [&](int buf, int s) {
            const int kb = s * 32;
            #pragma unroll
            for (int mi = 0; mi < 4; mi++) {
                const int row = wm + mi * 16 + a_row_l;
                const uint32_t off = (uint32_t)row * 128
                    + (((uint32_t)(kb + a_kb_l)) ^ (((uint32_t)row & 7) << 4));
                LDSM_X4(ah[buf][mi][0], ah[buf][mi][1], ah[buf][mi][2], ah[buf][mi][3],
                        As + off);
            }
            #pragma unroll
            for (int nj2 = 0; nj2 < 2; nj2++) {
                const int nr = wn + nj2 * 16 + b_n_l;
                const uint32_t off = (uint32_t)nr * 128
                    + (((uint32_t)(kb + b_kb_l)) ^ (((uint32_t)nr & 7) << 4));
                LDSM_X4(bh[buf][2*nj2][0], bh[buf][2*nj2][1],
                        bh[buf][2*nj2+1][0], bh[buf][2*nj2+1][1], Bs + off);
            }
        };

        frags(0, 0);
        #pragma unroll
        for (int s = 0; s < 4; s++) {     // 4 k16 steps per 64-chunk
            const int cur = s & 1;
            if (s < 3) frags(cur ^ 1, s + 1);
            #pragma unroll
            for (int mi = 0; mi < 4; mi++)
                #pragma unroll
                for (int nj = 0; nj < 4; nj++)
                    mma_f16(acc[mi][nj], ah[cur][mi], bh[cur][nj]);
        }
    }

    // ---------------- epilogue ----------------
    const int g  = lane >> 2;
    const int t4 = lane & 3;
    #pragma unroll
    for (int mi = 0; mi < 4; mi++) {
        const int r0 = m0 + wm + mi * 16 + g;
        const int r1 = r0 + 8;
        #pragma unroll
        for (int nj = 0; nj < 4; nj++) {
            const int col = n0 + wn + nj * 8 + t4 * 2;
            float c0 = acc[mi][nj][0], c1 = acc[mi][nj][1];
            float c2 = acc[mi][nj][2], c3 = acc[mi][nj][3];
            if (EPI == 0) {
                float2 v0; v0.x = c0; v0.y = c1;
                float2 v1; v1.x = c2; v1.y = c3;
                *(float2*)(Cf + (size_t)r0 * ldc + col) = v0;
                *(float2*)(Cf + (size_t)r1 * ldc + col) = v1;
            } else {
                __half2 h0 = __floats2half2_rn(c0, c1);
                __half2 h1 = __floats2half2_rn(c2, c3);
                *(__half2*)(Ch + (size_t)r0 * ldc + col) = h0;
                *(__half2*)(Ch + (size_t)r1 * ldc + col) = h1;
            }
        }
    }
}

// ---------------------------------------------------------------------------
// Launch: magcol(1) -> fused_prep(2) -> gemm1(3) -> gemm2(4) -> gemm3(5)
// Chain:  T1 = (cs⊙dir) @ lora_A^T ;  QT = T1 @ lora_B^T ;  out = x @ QT^T
// ---------------------------------------------------------------------------
extern "C" void kernel_launch(void* const* d_in, const int* in_sizes, int n_in,
                              void* d_out, int out_size) {
    const float* x         = (const float*)d_in[0];
    const float* lora_A    = (const float*)d_in[1];
    const float* lora_B    = (const float*)d_in[2];
    const float* magnitude = (const float*)d_in[3];
    const float* direction = (const float*)d_in[4];
    float* out = (float*)d_out;

    f16 *x16, *lA, *lB, *ds, *T1, *QT;
    cudaGetSymbolAddress((void**)&x16, g_x16);
    cudaGetSymbolAddress((void**)&lA, g_lA);
    cudaGetSymbolAddress((void**)&lB, g_lB);
    cudaGetSymbolAddress((void**)&ds, g_ds);
    cudaGetSymbolAddress((void**)&T1, g_T1);
    cudaGetSymbolAddress((void**)&QT, g_QT);

    constexpr int SM = 2 * 128 * 128 * 3;   // 98304 bytes
    cudaFuncSetAttribute(gemm_f16<0>, cudaFuncAttributeMaxDynamicSharedMemorySize, SM);
    cudaFuncSetAttribute(gemm_f16<1>, cudaFuncAttributeMaxDynamicSharedMemorySize, SM);

    // 1: norms (must precede prep: dir is pre-scaled by cs)
    magcol_kernel<<<DDIM, 256>>>(magnitude, direction);
    // 2: fused conversions (x, lora_A, lora_B plain; dir scaled by cs)
    fused_prep<<<BX + 3 * BD, 256>>>(x, lora_A, lora_B, direction);

    dim3 gs(DDIM / 128, DDIM / 128);   // 256 CTAs
    dim3 gb(DDIM / 128, NTOK / 128);   // 1024 CTAs

    // 3: T1 = (cs⊙dir) @ lora_A^T   (fp16 out)
    gemm_f16<1><<<gs, 256, SM>>>(ds, lA, nullptr, T1);
    // 4: QT = T1 @ lora_B^T          (fp16 out)
    gemm_f16<1><<<gs, 256, SM>>>(T1, lB, nullptr, QT);
    // 5: out = x @ QT^T              (fp32 out)
    gemm_f16<0><<<gb, 256, SM>>>(x16, QT, out, nullptr);
}

// round 12
// speedup vs baseline: 2.8296x; 1.0671x over previous
#include <cuda_runtime.h>
#include <cuda_fp16.h>
#include <cstdint>
#include <math.h>

typedef __half f16;

#define NTOK 8192
#define DDIM 2048
#define KDIM 2048
#define SCALING_F (16.0f / 2048.0f)
#define EPS_F 1e-12f

// ---------------------------------------------------------------------------
// Static device scratch
// ---------------------------------------------------------------------------
__device__ f16 g_x16[(size_t)NTOK * DDIM];     // x
__device__ f16 g_lA [(size_t)DDIM * DDIM];     // lora_A
__device__ f16 g_lB [(size_t)DDIM * DDIM];     // lora_B
__device__ f16 g_ds [(size_t)DDIM * DDIM];     // cs ⊙ direction
__device__ f16 g_T1 [(size_t)DDIM * DDIM];     // T1 = (cs⊙dir) @ lora_A^T
__device__ f16 g_QT [(size_t)DDIM * DDIM];     // QT = T1 @ lora_B^T
__device__ float g_cs[DDIM];

// ---------------------------------------------------------------------------
// PTX helpers — standard sm_80 features only
// ---------------------------------------------------------------------------
__device__ __forceinline__ uint32_t smem_u32(const void* p) {
    uint32_t a;
    asm("{ .reg .u64 t; cvta.to.shared.u64 t, %1; cvt.u32.u64 %0, t; }" : "=r"(a) : "l"(p));
    return a;
}
__device__ __forceinline__ void cp_async16(uint32_t dst, const void* src) {
    asm volatile("cp.async.cg.shared.global [%0], [%1], 16;" :: "r"(dst), "l"(src));
}
__device__ __forceinline__ void cp_commit() { asm volatile("cp.async.commit_group;" ::: "memory"); }
template <int N>
__device__ __forceinline__ void cp_wait() { asm volatile("cp.async.wait_group %0;" :: "n"(N) : "memory"); }

#define LDSM_X4(r0, r1, r2, r3, addr) \
    asm volatile("ldmatrix.sync.aligned.m8n8.x4.shared.b16 {%0,%1,%2,%3}, [%4];" \
        : "=r"(r0), "=r"(r1), "=r"(r2), "=r"(r3) : "r"(addr))

__device__ __forceinline__ void mma_f16(float* c, const uint32_t* a, const uint32_t* b) {
    asm volatile(
        "mma.sync.aligned.m16n8k16.row.col.f32.f16.f16.f32 "
        "{%0,%1,%2,%3}, {%4,%5,%6,%7}, {%8,%9}, {%0,%1,%2,%3};"
        : "+f"(c[0]), "+f"(c[1]), "+f"(c[2]), "+f"(c[3])
        : "r"(a[0]), "r"(a[1]), "r"(a[2]), "r"(a[3]), "r"(b[0]), "r"(b[1]));
}

// ---------------------------------------------------------------------------
// Prep 1: cs[o] = ||magnitude|| * SCALING / max(||direction[o,:]||, eps)
// ---------------------------------------------------------------------------
__global__ void magcol_kernel(const float* __restrict__ magnitude,
                              const float* __restrict__ direction) {
    int o = blockIdx.x;
    const float* row = direction + (size_t)o * DDIM;
    float sm = 0.0f, sd = 0.0f;
    for (int i = threadIdx.x; i < DDIM; i += 256) {
        float a = magnitude[i];  sm += a * a;
        float b = row[i];        sd += b * b;
    }
    __shared__ float rm[256], rd[256];
    rm[threadIdx.x] = sm; rd[threadIdx.x] = sd;
    __syncthreads();
    for (int off = 128; off > 0; off >>= 1) {
        if (threadIdx.x < off) {
            rm[threadIdx.x] += rm[threadIdx.x + off];
            rd[threadIdx.x] += rd[threadIdx.x + off];
        }
        __syncthreads();
    }
    if (threadIdx.x == 0)
        g_cs[o] = sqrtf(rm[0]) * SCALING_F / fmaxf(sqrtf(rd[0]), EPS_F);
}

// ---------------------------------------------------------------------------
// Prep 2: fused fp32 -> fp16 conversions (8 elems/thread, 16B stores)
// ---------------------------------------------------------------------------
__device__ __forceinline__ void cvt8(const float* __restrict__ in, f16* __restrict__ out,
                                     int i, float s) {
    float4 a = ((const float4*)in)[i * 2];
    float4 b = ((const float4*)in)[i * 2 + 1];
    __half2 h0 = __floats2half2_rn(a.x * s, a.y * s);
    __half2 h1 = __floats2half2_rn(a.z * s, a.w * s);
    __half2 h2 = __floats2half2_rn(b.x * s, b.y * s);
    __half2 h3 = __floats2half2_rn(b.z * s, b.w * s);
    uint4 v; v.x = *(uint32_t*)&h0; v.y = *(uint32_t*)&h1;
    v.z = *(uint32_t*)&h2; v.w = *(uint32_t*)&h3;
    ((uint4*)out)[i] = v;
}

#define NX8 ((NTOK * DDIM) / 8)
#define ND8 ((DDIM * DDIM) / 8)
#define BX  (NX8 / 256)
#define BD  (ND8 / 256)

__global__ void fused_prep(const float* __restrict__ x,
                           const float* __restrict__ lA,
                           const float* __restrict__ lB,
                           const float* __restrict__ dir) {
    int b = blockIdx.x;
    if (b < BX) {
        cvt8(x, g_x16, b * 256 + threadIdx.x, 1.0f);
    } else if (b < BX + BD) {
        cvt8(lA, g_lA, (b - BX) * 256 + threadIdx.x, 1.0f);
    } else if (b < BX + 2 * BD) {
        cvt8(lB, g_lB, (b - BX - BD) * 256 + threadIdx.x, 1.0f);
    } else {
        int i = (b - BX - 2 * BD) * 256 + threadIdx.x;
        int row = (i * 8) / DDIM;        // 8 | DDIM -> row constant across the 8
        cvt8(dir, g_ds, i, g_cs[row]);
    }
}

// ---------------------------------------------------------------------------
// fp16 GEMM (single pass): C[M,N] = A[M,K] * B[N,K]^T, K = 2048.
// CTA tile 128x256, warp tile 64x64 (2x4 warp grid), BK=64, S=3 stages
// (stage 48KB: A 16KB | B 32KB), SW128 XOR swizzle, double-buffered frags.
// Per k16 step: 8 LDSM.x4 -> 32 MMAs (ratio 0.25).
// EPI=0: fp32 out.  EPI=1: fp16 out.
// ---------------------------------------------------------------------------
template <int EPI>
__global__ __launch_bounds__(256, 1)
void gemm_f16(const f16* __restrict__ A_g, const f16* __restrict__ B_g,
              float* __restrict__ Cf, f16* __restrict__ Ch)
{
    extern __shared__ __align__(128) char smem[];
    const uint32_t sb = smem_u32(smem);

    constexpr int K = KDIM, BK = 64, NC = K / BK, S = 3;
    constexpr uint32_t TA = 128 * 128;       // 16 KB (A: 128 rows x 128 B)
    constexpr uint32_t TB = 256 * 128;       // 32 KB (B: 256 rows x 128 B)
    constexpr uint32_t STAGE = TA + TB;      // 48 KB

    const int tid = threadIdx.x;
    const int m0 = blockIdx.y * 128;
    const int n0 = blockIdx.x * 256;
    const int ldc = gridDim.x * 256;
    const int wid = tid >> 5, lane = tid & 31;
    const int wm = (wid >> 2) * 64;   // 0 / 64
    const int wn = (wid & 3) * 64;    // 0/64/128/192

    const int lrow = tid >> 3;        // 0..31
    const int lg   = tid & 7;         // 16B group in 128B row
    const f16* gpA = A_g + (size_t)m0 * K;
    const f16* gpB = B_g + (size_t)n0 * K;

    auto load_stage = [&](int slot, int c) {
        const uint32_t base = sb + (uint32_t)slot * STAGE;
        const int k0 = c * BK + lg * 8;
        #pragma unroll
        for (int j = 0; j < 4; j++) {          // A: 128 rows
            const int row = lrow + 32 * j;
            uint32_t off = (uint32_t)row * 128 + (uint32_t)lg * 16;
            off ^= ((uint32_t)row & 7) << 4;
            cp_async16(base + off, gpA + (size_t)row * K + k0);
        }
        #pragma unroll
        for (int j = 0; j < 8; j++) {          // B: 256 rows
            const int row = lrow + 32 * j;
            uint32_t off = (uint32_t)row * 128 + (uint32_t)lg * 16;
            off ^= ((uint32_t)row & 7) << 4;
            cp_async16(base + TA + off, gpB + (size_t)row * K + k0);
        }
        cp_commit();
    };

    float acc[4][8][4];
    #pragma unroll
    for (int a = 0; a < 4; a++)
        #pragma unroll
        for (int b = 0; b < 8; b++)
            #pragma unroll
            for (int q = 0; q < 4; q++) acc[a][b][q] = 0.0f;

    load_stage(0, 0);
    load_stage(1, 1);

    // ldmatrix lane components
    const int a_row_l = lane & 15;
    const int a_kb_l  = (lane >> 4) * 16;
    const int b_n_l   = (lane & 7) + ((lane >> 4) << 3);
    const int b_kb_l  = ((lane >> 3) & 1) * 16;

    // double-buffered fragments
    uint32_t ah[2][4][4], bh[2][8][2];

    for (int c = 0; c < NC; c++) {
        if (c + 1 < NC) cp_wait<1>(); else cp_wait<0>();
        __syncthreads();
        if (c + 2 < NC) load_stage((c + 2) % S, c + 2);

        const uint32_t stg = sb + (uint32_t)(c % S) * STAGE;
        const uint32_t As = stg, Bs = stg + TA;

        auto frags = [&](int buf, int s) {
            const int kb = s * 32;
            #pragma unroll
            for (int mi = 0; mi < 4; mi++) {
                const int row = wm + mi * 16 + a_row_l;
                const uint32_t off = (uint32_t)row * 128
                    + (((uint32_t)(kb + a_kb_l)) ^ (((uint32_t)row & 7) << 4));
                LDSM_X4(ah[buf][mi][0], ah[buf][mi][1], ah[buf][mi][2], ah[buf][mi][3],
                        As + off);
            }
            #pragma unroll
            for (int nj2 = 0; nj2 < 4; nj2++) {
                const int nr = wn + nj2 * 16 + b_n_l;
                const uint32_t off = (uint32_t)nr * 128
                    + (((uint32_t)(kb + b_kb_l)) ^ (((uint32_t)nr & 7) << 4));
                LDSM_X4(bh[buf][2*nj2][0], bh[buf][2*nj2][1],
                        bh[buf][2*nj2+1][0], bh[buf][2*nj2+1][1], Bs + off);
            }
        };

        frags(0, 0);
        #pragma unroll
        for (int s = 0; s < 4; s++) {     // 4 k16 steps per 64-chunk
            const int cur = s & 1;
            if (s < 3) frags(cur ^ 1, s + 1);
            #pragma unroll
            for (int mi = 0; mi < 4; mi++)
                #pragma unroll
                for (int nj = 0; nj < 8; nj++)
                    mma_f16(acc[mi][nj], ah[cur][mi], bh[cur][nj]);
        }
    }

    // ---------------- epilogue ----------------
    const int g  = lane >> 2;
    const int t4 = lane & 3;
    #pragma unroll
    for (int mi = 0; mi < 4; mi++) {
        const int r0 = m0 + wm + mi * 16 + g;
        const int r1 = r0 + 8;
        #pragma unroll
        for (int nj = 0; nj < 8; nj++) {
            const int col = n0 + wn + nj * 8 + t4 * 2;
            float c0 = acc[mi][nj][0], c1 = acc[mi][nj][1];
            float c2 = acc[mi][nj][2], c3 = acc[mi][nj][3];
            if (EPI == 0) {
                float2 v0; v0.x = c0; v0.y = c1;
                float2 v1; v1.x = c2; v1.y = c3;
                *(float2*)(Cf + (size_t)r0 * ldc + col) = v0;
                *(float2*)(Cf + (size_t)r1 * ldc + col) = v1;
            } else {
                __half2 h0 = __floats2half2_rn(c0, c1);
                __half2 h1 = __floats2half2_rn(c2, c3);
                *(__half2*)(Ch + (size_t)r0 * ldc + col) = h0;
                *(__half2*)(Ch + (size_t)r1 * ldc + col) = h1;
            }
        }
    }
}

// ---------------------------------------------------------------------------
// Launch: magcol(1) -> fused_prep(2) -> gemm1(3) -> gemm2(4) -> gemm3(5)
// Chain:  T1 = (cs⊙dir) @ lora_A^T ;  QT = T1 @ lora_B^T ;  out = x @ QT^T
// ---------------------------------------------------------------------------
extern "C" void kernel_launch(void* const* d_in, const int* in_sizes, int n_in,
                              void* d_out, int out_size) {
    const float* x         = (const float*)d_in[0];
    const float* lora_A    = (const float*)d_in[1];
    const float* lora_B    = (const float*)d_in[2];
    const float* magnitude = (const float*)d_in[3];
    const float* direction = (const float*)d_in[4];
    float* out = (float*)d_out;

    f16 *x16, *lA, *lB, *ds, *T1, *QT;
    cudaGetSymbolAddress((void**)&x16, g_x16);
    cudaGetSymbolAddress((void**)&lA, g_lA);
    cudaGetSymbolAddress((void**)&lB, g_lB);
    cudaGetSymbolAddress((void**)&ds, g_ds);
    cudaGetSymbolAddress((void**)&T1, g_T1);
    cudaGetSymbolAddress((void**)&QT, g_QT);

    constexpr int SM = 3 * (128 * 128 + 256 * 128);   // 147456 bytes
    cudaFuncSetAttribute(gemm_f16<0>, cudaFuncAttributeMaxDynamicSharedMemorySize, SM);
    cudaFuncSetAttribute(gemm_f16<1>, cudaFuncAttributeMaxDynamicSharedMemorySize, SM);

    // 1: norms (must precede prep: dir is pre-scaled by cs)
    magcol_kernel<<<DDIM, 256>>>(magnitude, direction);
    // 2: fused conversions
    fused_prep<<<BX + 3 * BD, 256>>>(x, lora_A, lora_B, direction);

    dim3 gs(DDIM / 256, DDIM / 128);   // (8, 16) = 128 CTAs  (single wave)
    dim3 gb(DDIM / 256, NTOK / 128);   // (8, 64) = 512 CTAs

    // 3: T1 = (cs⊙dir) @ lora_A^T   (fp16 out)
    gemm_f16<1><<<gs, 256, SM>>>(ds, lA, nullptr, T1);
    // 4: QT = T1 @ lora_B^T          (fp16 out)
    gemm_f16<1><<<gs, 256, SM>>>(T1, lB, nullptr, QT);
    // 5: out = x @ QT^T              (fp32 out)
    gemm_f16<0><<<gb, 256, SM>>>(x16, QT, out, nullptr);
}

// round 13
// speedup vs baseline: 2.8512x; 1.0076x over previous
#include <cuda_runtime.h>
#include <cuda_fp16.h>
#include <cstdint>
#include <math.h>

typedef __half f16;

#define NTOK 8192
#define DDIM 2048
#define KDIM 2048
#define SCALING_F (16.0f / 2048.0f)
#define EPS_F 1e-12f

// ---------------------------------------------------------------------------
// Static device scratch
// ---------------------------------------------------------------------------
__device__ f16 g_x16[(size_t)NTOK * DDIM];     // x
__device__ f16 g_lA [(size_t)DDIM * DDIM];     // lora_A
__device__ f16 g_lB [(size_t)DDIM * DDIM];     // lora_B
__device__ f16 g_ds [(size_t)DDIM * DDIM];     // cs ⊙ direction
__device__ f16 g_T1 [(size_t)DDIM * DDIM];     // T1 = (cs⊙dir) @ lora_A^T
__device__ f16 g_QT [(size_t)DDIM * DDIM];     // QT = T1 @ lora_B^T
__device__ float g_cs[DDIM];

// ---------------------------------------------------------------------------
// PTX helpers — standard sm_80 features only
// ---------------------------------------------------------------------------
__device__ __forceinline__ uint32_t smem_u32(const void* p) {
    uint32_t a;
    asm("{ .reg .u64 t; cvta.to.shared.u64 t, %1; cvt.u32.u64 %0, t; }" : "=r"(a) : "l"(p));
    return a;
}
__device__ __forceinline__ void cp_async16(uint32_t dst, const void* src) {
    asm volatile("cp.async.cg.shared.global [%0], [%1], 16;" :: "r"(dst), "l"(src));
}
__device__ __forceinline__ void cp_commit() { asm volatile("cp.async.commit_group;" ::: "memory"); }
template <int N>
__device__ __forceinline__ void cp_wait() { asm volatile("cp.async.wait_group %0;" :: "n"(N) : "memory"); }

#define LDSM_X4(r0, r1, r2, r3, addr) \
    asm volatile("ldmatrix.sync.aligned.m8n8.x4.shared.b16 {%0,%1,%2,%3}, [%4];" \
        : "=r"(r0), "=r"(r1), "=r"(r2), "=r"(r3) : "r"(addr))

__device__ __forceinline__ void mma_f16(float* c, const uint32_t* a, const uint32_t* b) {
    asm volatile(
        "mma.sync.aligned.m16n8k16.row.col.f32.f16.f16.f32 "
        "{%0,%1,%2,%3}, {%4,%5,%6,%7}, {%8,%9}, {%0,%1,%2,%3};"
        : "+f"(c[0]), "+f"(c[1]), "+f"(c[2]), "+f"(c[3])
        : "r"(a[0]), "r"(a[1]), "r"(a[2]), "r"(a[3]), "r"(b[0]), "r"(b[1]));
}

// ---------------------------------------------------------------------------
// Prep 1: cs[o] = ||magnitude|| * SCALING / max(||direction[o,:]||, eps)
// ---------------------------------------------------------------------------
__global__ void magcol_kernel(const float* __restrict__ magnitude,
                              const float* __restrict__ direction) {
    int o = blockIdx.x;
    const float* row = direction + (size_t)o * DDIM;
    float sm = 0.0f, sd = 0.0f;
    for (int i = threadIdx.x; i < DDIM; i += 256) {
        float a = magnitude[i];  sm += a * a;
        float b = row[i];        sd += b * b;
    }
    __shared__ float rm[256], rd[256];
    rm[threadIdx.x] = sm; rd[threadIdx.x] = sd;
    __syncthreads();
    for (int off = 128; off > 0; off >>= 1) {
        if (threadIdx.x < off) {
            rm[threadIdx.x] += rm[threadIdx.x + off];
            rd[threadIdx.x] += rd[threadIdx.x + off];
        }
        __syncthreads();
    }
    if (threadIdx.x == 0)
        g_cs[o] = sqrtf(rm[0]) * SCALING_F / fmaxf(sqrtf(rd[0]), EPS_F);
}

// ---------------------------------------------------------------------------
// Prep 2: fused fp32 -> fp16 conversions (8 elems/thread, 16B stores)
// ---------------------------------------------------------------------------
__device__ __forceinline__ void cvt8(const float* __restrict__ in, f16* __restrict__ out,
                                     int i, float s) {
    float4 a = ((const float4*)in)[i * 2];
    float4 b = ((const float4*)in)[i * 2 + 1];
    __half2 h0 = __floats2half2_rn(a.x * s, a.y * s);
    __half2 h1 = __floats2half2_rn(a.z * s, a.w * s);
    __half2 h2 = __floats2half2_rn(b.x * s, b.y * s);
    __half2 h3 = __floats2half2_rn(b.z * s, b.w * s);
    uint4 v; v.x = *(uint32_t*)&h0; v.y = *(uint32_t*)&h1;
    v.z = *(uint32_t*)&h2; v.w = *(uint32_t*)&h3;
    ((uint4*)out)[i] = v;
}

#define NX8 ((NTOK * DDIM) / 8)
#define ND8 ((DDIM * DDIM) / 8)
#define BX  (NX8 / 256)
#define BD  (ND8 / 256)

__global__ void fused_prep(const float* __restrict__ x,
                           const float* __restrict__ lA,
                           const float* __restrict__ lB,
                           const float* __restrict__ dir) {
    int b = blockIdx.x;
    if (b < BX) {
        cvt8(x, g_x16, b * 256 + threadIdx.x, 1.0f);
    } else if (b < BX + BD) {
        cvt8(lA, g_lA, (b - BX) * 256 + threadIdx.x, 1.0f);
    } else if (b < BX + 2 * BD) {
        cvt8(lB, g_lB, (b - BX - BD) * 256 + threadIdx.x, 1.0f);
    } else {
        int i = (b - BX - 2 * BD) * 256 + threadIdx.x;
        int row = (i * 8) / DDIM;        // 8 | DDIM -> row constant across the 8
        cvt8(dir, g_ds, i, g_cs[row]);
    }
}

// ---------------------------------------------------------------------------
// PERSISTENT fp16 GEMM (single pass): C = A[M,K] * B[N,K]^T, K = 2048.
// CTA tile 128x256, warp tile 64x64, BK=64, S=3 stages (48 KB each).
// grid = #SMs; tiles walked stride-grid; the cp.async pipeline continues
// ACROSS tiles (next tile's chunks prefetched under this tile's last chunks;
// epilogue overlaps them).  EPI=0: fp32 out.  EPI=1: fp16 out.
// ---------------------------------------------------------------------------
template <int EPI>
__global__ __launch_bounds__(256, 1)
void gemm_f16(const f16* __restrict__ A_g, const f16* __restrict__ B_g,
              float* __restrict__ Cf, f16* __restrict__ Ch,
              int tilesM, int tilesN)
{
    extern __shared__ __align__(128) char smem[];
    const uint32_t sb = smem_u32(smem);

    constexpr int K = KDIM, BK = 64, NC = K / BK, S = 3;
    constexpr uint32_t TA = 128 * 128;       // 16 KB
    constexpr uint32_t TB = 256 * 128;       // 32 KB
    constexpr uint32_t STAGE = TA + TB;      // 48 KB

    const int T = tilesM * tilesN;
    const int ldc = tilesN * 256;
    const int tid = threadIdx.x;
    const int wid = tid >> 5, lane = tid & 31;
    const int wm = (wid >> 2) * 64;
    const int wn = (wid & 3) * 64;

    const int lrow = tid >> 3;
    const int lg   = tid & 7;

    const int a_row_l = lane & 15;
    const int a_kb_l  = (lane >> 4) * 16;
    const int b_n_l   = (lane & 7) + ((lane >> 4) << 3);
    const int b_kb_l  = ((lane >> 3) & 1) * 16;

    int tile = blockIdx.x;
    if (tile >= T) return;
    int tm = tile / tilesN, tn = tile - tm * tilesN;
    const f16* cA = A_g + (size_t)tm * 128 * K;
    const f16* cB = B_g + (size_t)tn * 256 * K;

    auto load_stage = [&](int slot, const f16* pA, const f16* pB, int k0) {
        const uint32_t base = sb + (uint32_t)slot * STAGE;
        const int ks = k0 + lg * 8;
        #pragma unroll
        for (int j = 0; j < 4; j++) {          // A: 128 rows
            const int row = lrow + 32 * j;
            uint32_t off = (uint32_t)row * 128 + (uint32_t)lg * 16;
            off ^= ((uint32_t)row & 7) << 4;
            cp_async16(base + off, pA + (size_t)row * K + ks);
        }
        #pragma unroll
        for (int j = 0; j < 8; j++) {          // B: 256 rows
            const int row = lrow + 32 * j;
            uint32_t off = (uint32_t)row * 128 + (uint32_t)lg * 16;
            off ^= ((uint32_t)row & 7) << 4;
            cp_async16(base + TA + off, pB + (size_t)row * K + ks);
        }
        cp_commit();
    };

    load_stage(0, cA, cB, 0);
    load_stage(1, cA, cB, BK);
    int scur = 0, sld = 2;   // consume slot / next load slot (rotate mod S forever)

    uint32_t ah[2][4][4], bh[2][8][2];

    while (true) {
        const int ntile = tile + gridDim.x;
        const bool have_next = ntile < T;
        const f16 *nA = cA, *nB = cB;
        int nm = tm, nn = tn;
        if (have_next) {
            nm = ntile / tilesN; nn = ntile - nm * tilesN;
            nA = A_g + (size_t)nm * 128 * K;
            nB = B_g + (size_t)nn * 256 * K;
        }

        float acc[4][8][4];
        #pragma unroll
        for (int a = 0; a < 4; a++)
            #pragma unroll
            for (int b = 0; b < 8; b++)
                #pragma unroll
                for (int q = 0; q < 4; q++) acc[a][b][q] = 0.0f;

        for (int c = 0; c < NC; c++) {
            if (c == NC - 1 && !have_next) cp_wait<0>(); else cp_wait<1>();
            __syncthreads();

            if (c + 2 < NC)            load_stage(sld, cA, cB, (c + 2) * BK);
            else if (have_next)        load_stage(sld, nA, nB, (c + 2 - NC) * BK);

            const uint32_t stg = sb + (uint32_t)scur * STAGE;
            const uint32_t As = stg, Bs = stg + TA;

            auto frags = [&](int buf, int s) {
                const int kb = s * 32;
                #pragma unroll
                for (int mi = 0; mi < 4; mi++) {
                    const int row = wm + mi * 16 + a_row_l;
                    const uint32_t off = (uint32_t)row * 128
                        + (((uint32_t)(kb + a_kb_l)) ^ (((uint32_t)row & 7) << 4));
                    LDSM_X4(ah[buf][mi][0], ah[buf][mi][1], ah[buf][mi][2], ah[buf][mi][3],
                            As + off);
                }
                #pragma unroll
                for (int nj2 = 0; nj2 < 4; nj2++) {
                    const int nr = wn + nj2 * 16 + b_n_l;
                    const uint32_t off = (uint32_t)nr * 128
                        + (((uint32_t)(kb + b_kb_l)) ^ (((uint32_t)nr & 7) << 4));
                    LDSM_X4(bh[buf][2*nj2][0], bh[buf][2*nj2][1],
                            bh[buf][2*nj2+1][0], bh[buf][2*nj2+1][1], Bs + off);
                }
            };

            frags(0, 0);
            #pragma unroll
            for (int s = 0; s < 4; s++) {
                const int cur = s & 1;
                if (s < 3) frags(cur ^ 1, s + 1);
                #pragma unroll
                for (int mi = 0; mi < 4; mi++)
                    #pragma unroll
                    for (int nj = 0; nj < 8; nj++)
                        mma_f16(acc[mi][nj], ah[cur][mi], bh[cur][nj]);
            }

            if (++scur == S) scur = 0;
            if (++sld == S) sld = 0;
        }

        // ---------------- epilogue (overlaps next tile's loads) ----------
        const int m0 = tm * 128, n0 = tn * 256;
        const int g  = lane >> 2;
        const int t4 = lane & 3;
        #pragma unroll
        for (int mi = 0; mi < 4; mi++) {
            const int r0 = m0 + wm + mi * 16 + g;
            const int r1 = r0 + 8;
            #pragma unroll
            for (int nj = 0; nj < 8; nj++) {
                const int col = n0 + wn + nj * 8 + t4 * 2;
                float c0 = acc[mi][nj][0], c1 = acc[mi][nj][1];
                float c2 = acc[mi][nj][2], c3 = acc[mi][nj][3];
                if (EPI == 0) {
                    float2 v0; v0.x = c0; v0.y = c1;
                    float2 v1; v1.x = c2; v1.y = c3;
                    *(float2*)(Cf + (size_t)r0 * ldc + col) = v0;
                    *(float2*)(Cf + (size_t)r1 * ldc + col) = v1;
                } else {
                    __half2 h0 = __floats2half2_rn(c0, c1);
                    __half2 h1 = __floats2half2_rn(c2, c3);
                    *(__half2*)(Ch + (size_t)r0 * ldc + col) = h0;
                    *(__half2*)(Ch + (size_t)r1 * ldc + col) = h1;
                }
            }
        }

        if (!have_next) break;
        tile = ntile; tm = nm; tn = nn; cA = nA; cB = nB;
    }
}

// ---------------------------------------------------------------------------
// Launch: magcol(1) -> fused_prep(2) -> gemm1(3) -> gemm2(4) -> gemm3(5)
// Chain:  T1 = (cs⊙dir) @ lora_A^T ;  QT = T1 @ lora_B^T ;  out = x @ QT^T
// ---------------------------------------------------------------------------
extern "C" void kernel_launch(void* const* d_in, const int* in_sizes, int n_in,
                              void* d_out, int out_size) {
    const float* x         = (const float*)d_in[0];
    const float* lora_A    = (const float*)d_in[1];
    const float* lora_B    = (const float*)d_in[2];
    const float* magnitude = (const float*)d_in[3];
    const float* direction = (const float*)d_in[4];
    float* out = (float*)d_out;

    f16 *x16, *lA, *lB, *ds, *T1, *QT;
    cudaGetSymbolAddress((void**)&x16, g_x16);
    cudaGetSymbolAddress((void**)&lA, g_lA);
    cudaGetSymbolAddress((void**)&lB, g_lB);
    cudaGetSymbolAddress((void**)&ds, g_ds);
    cudaGetSymbolAddress((void**)&T1, g_T1);
    cudaGetSymbolAddress((void**)&QT, g_QT);

    constexpr int SM = 3 * (128 * 128 + 256 * 128);   // 147456 bytes
    cudaFuncSetAttribute(gemm_f16<0>, cudaFuncAttributeMaxDynamicSharedMemorySize, SM);
    cudaFuncSetAttribute(gemm_f16<1>, cudaFuncAttributeMaxDynamicSharedMemorySize, SM);

    int nsm = 148;
    cudaDeviceGetAttribute(&nsm, cudaDevAttrMultiProcessorCount, 0);

    // 1: norms (must precede prep: dir is pre-scaled by cs)
    magcol_kernel<<<DDIM, 256>>>(magnitude, direction);
    // 2: fused conversions
    fused_prep<<<BX + 3 * BD, 256>>>(x, lora_A, lora_B, direction);

    const int tsN = DDIM / 256;            // 8
    const int tsM_s = DDIM / 128;          // 16  -> 128 tiles (small GEMMs)
    const int tsM_b = NTOK / 128;          // 64  -> 512 tiles (big GEMM)

    // 3: T1 = (cs⊙dir) @ lora_A^T   (fp16 out; 128 tiles <= grid, 1 tile/CTA)
    gemm_f16<1><<<nsm, 256, SM>>>(ds, lA, nullptr, T1, tsM_s, tsN);
    // 4: QT = T1 @ lora_B^T          (fp16 out)
    gemm_f16<1><<<nsm, 256, SM>>>(T1, lB, nullptr, QT, tsM_s, tsN);
    // 5: out = x @ QT^T              (fp32 out; persistent walk of 512 tiles)
    gemm_f16<0><<<nsm, 256, SM>>>(x16, QT, out, nullptr, tsM_b, tsN);
}